// round 10
// baseline (speedup 1.0000x reference)
#include <cuda_runtime.h>
#include <cuda_bf16.h>

#define N_USERS 100000
#define N_ITEMS 50000
#define N_NODES (N_USERS + N_ITEMS)
#define D 64
#define F 768
#define N_EDGES 4800000
#define BATCH 4096
#define LN_EPS 1e-5f

#define SCAN_CHUNK 1024
#define NSCAN ((N_NODES + SCAN_CHUNK - 1) / SCAN_CHUNK)   // 147

#define N_EDGE4 (N_EDGES / 4)                             // 1200000 exact
#define GEMM_BLOCKS ((N_ITEMS + 63) / 64)                 // 782
#define GEMM_A 300
#define GEMM_B (GEMM_BLOCKS - GEMM_A)                     // 482
#define HIST4_BLOCKS ((N_EDGE4 + 255) / 256)              // 4688
#define FILL_BLOCKS ((N_EDGES + 255) / 256)               // 18750 (scalar, 1 edge/thread)
#define INIT_BLOCKS 1024
#define COMBO_A_BLOCKS (GEMM_A + HIST4_BLOCKS + INIT_BLOCKS)
#define COMBO_B_BLOCKS (GEMM_B + FILL_BLOCKS)

#define GATHER_BLOCKS (3 * BATCH / 4)                     // 3072
#define LOSS_BLOCKS (N_ITEMS * D / 4 / 256)               // 3125 exact
#define OUT_BLOCKS (GATHER_BLOCKS + LOSS_BLOCKS)

// ---- scratch (device globals) ----
__device__ float g_e0[N_NODES * D];
__device__ float g_e1[N_NODES * D];
__device__ float g_e2[N_NODES * D];
__device__ float g_e3[N_NODES * D];
__device__ float g_ic[N_ITEMS * D];
__device__ int   g_deg[N_NODES];
__device__ int   g_off[N_NODES + 1];
__device__ int   g_cursor[N_NODES];
__device__ int   g_blksum[NSCAN];
__device__ int   g_blkoff[NSCAN];
__device__ int   g_csr_src[N_EDGES];
__device__ float g_csr_w[N_EDGES];
__device__ float g_partials[LOSS_BLOCKS];

// packed f32x2 FMA (sm_103a FFMA2 — exact fp32)
__device__ __forceinline__ unsigned long long pack2(float lo, float hi) {
    unsigned long long r;
    asm("mov.b64 %0, {%1, %2};" : "=l"(r) : "f"(lo), "f"(hi));
    return r;
}
__device__ __forceinline__ void ffma2(unsigned long long& a,
                                      unsigned long long c,
                                      unsigned long long b) {
    asm("fma.rn.f32x2 %0, %1, %2, %0;" : "+l"(a) : "l"(c), "l"(b));
}
__device__ __forceinline__ float2 unpack2(unsigned long long v) {
    float2 r;
    asm("mov.b64 {%0, %1}, %2;" : "=f"(r.x), "=f"(r.y) : "l"(v));
    return r;
}

// ---------------------------------------------------------------------------
// GEMM tile body (FFMA2): one 64-item x 64-dim tile
// ---------------------------------------------------------------------------
__device__ void gemm_tile(int tile,
                          const float* __restrict__ cf,
                          const float* __restrict__ Wp,
                          const float* __restrict__ bp,
                          const float* __restrict__ wg,
                          const float* __restrict__ bg,
                          const float* __restrict__ item_emb) {
    __shared__ float Cs[32][68];
    __shared__ float Ws[32][64];
    __shared__ float wgs[32];
    __shared__ float gates[64];

    const int tid   = threadIdx.x;
    const int d     = tid & 63;
    const int r     = tid >> 6;
    const int item0 = tile * 64;

    unsigned long long acc2[8];
#pragma unroll
    for (int i = 0; i < 8; i++) acc2[i] = 0ull;
    float gp = 0.f;

    for (int kt = 0; kt < F; kt += 32) {
#pragma unroll
        for (int j = 0; j < 8; j++) {
            int l = tid + j * 256;
            int it = l >> 5, k = l & 31;
            int item = item0 + it;
            Cs[k][it] = (item < N_ITEMS) ? cf[item * F + kt + k] : 0.f;
        }
#pragma unroll
        for (int j = 0; j < 8; j++) {
            int l = tid + j * 256;
            int k = l >> 6, dd = l & 63;
            Ws[k][dd] = Wp[(kt + k) * D + dd];
        }
        if (tid < 32) wgs[tid] = wg[kt + tid];
        __syncthreads();

        if (tid < 64) {
#pragma unroll
            for (int k = 0; k < 32; k++) gp += Cs[k][tid] * wgs[k];
        }
#pragma unroll
        for (int k = 0; k < 32; k++) {
            float wv = Ws[k][d];
            unsigned long long w2 = pack2(wv, wv);
            const ulonglong2* cp = (const ulonglong2*)&Cs[k][r * 16];
#pragma unroll
            for (int q = 0; q < 4; q++) {
                ulonglong2 c = cp[q];
                ffma2(acc2[q * 2 + 0], c.x, w2);
                ffma2(acc2[q * 2 + 1], c.y, w2);
            }
        }
        __syncthreads();
    }

    if (tid < 64) gates[tid] = 1.f / (1.f + expf(-(gp + bg[0])));
    __syncthreads();

    const float bpd = bp[d];
#pragma unroll
    for (int p = 0; p < 8; p++) {
        float2 a = unpack2(acc2[p]);
#pragma unroll
        for (int h = 0; h < 2; h++) {
            int it = p * 2 + h;
            int item = item0 + r * 16 + it;
            if (item < N_ITEMS) {
                float ic = (h ? a.y : a.x) + bpd;
                g_ic[item * D + d] = ic;
                float g = gates[r * 16 + it];
                g_e0[(N_USERS + item) * D + d] =
                    (1.f - g) * item_emb[item * D + d] + g * ic;
            }
        }
    }
}

// ---------------------------------------------------------------------------
__global__ void zero_deg_kernel() {
    int i = blockIdx.x * blockDim.x + threadIdx.x;
    if (i < N_NODES) g_deg[i] = 0;
}

// combo_A: GEMM part 1 (LOW bid — starts first) || hist || user init
__global__ __launch_bounds__(256) void combo_a_kernel(
    const float* __restrict__ cf, const float* __restrict__ Wp,
    const float* __restrict__ bp, const float* __restrict__ wg,
    const float* __restrict__ bg, const float* __restrict__ item_emb,
    const float* __restrict__ user_emb, const int4* __restrict__ dst4) {
    const int bid = blockIdx.x;
    const int tid = threadIdx.x;
    if (bid < GEMM_A) {
        gemm_tile(bid, cf, Wp, bp, wg, bg, item_emb);
        return;
    }
    int b2 = bid - GEMM_A;
    if (b2 < HIST4_BLOCKS) {
        int i = b2 * 256 + tid;
        if (i < N_EDGE4) {
            int4 dd = dst4[i];
            atomicAdd(&g_deg[dd.x], 1);
            atomicAdd(&g_deg[dd.y], 1);
            atomicAdd(&g_deg[dd.z], 1);
            atomicAdd(&g_deg[dd.w], 1);
        }
        return;
    }
    int b3 = b2 - HIST4_BLOCKS;
    const int n = N_USERS * D / 4;
    const float4* u4 = (const float4*)user_emb;
    float4* e4 = (float4*)g_e0;
    for (int i = b3 * 256 + tid; i < n; i += INIT_BLOCKS * 256)
        e4[i] = u4[i];
}

// ---------------------------------------------------------------------------
// scans
// ---------------------------------------------------------------------------
__global__ __launch_bounds__(1024) void scan_sum_kernel() {
    __shared__ int sh[1024];
    int gid = blockIdx.x * SCAN_CHUNK + threadIdx.x;
    sh[threadIdx.x] = (gid < N_NODES) ? g_deg[gid] : 0;
    __syncthreads();
#pragma unroll
    for (int o = 512; o; o >>= 1) {
        if (threadIdx.x < o) sh[threadIdx.x] += sh[threadIdx.x + o];
        __syncthreads();
    }
    if (threadIdx.x == 0) g_blksum[blockIdx.x] = sh[0];
}

__global__ __launch_bounds__(256) void scan_top_kernel() {
    __shared__ int sh[2][256];
    int t = threadIdx.x;
    int v = (t < NSCAN) ? g_blksum[t] : 0;
    sh[0][t] = v;
    __syncthreads();
    int cur = 0;
#pragma unroll
    for (int o = 1; o < 256; o <<= 1) {
        int y = sh[cur][t];
        if (t >= o) y += sh[cur][t - o];
        sh[1 - cur][t] = y;
        __syncthreads();
        cur = 1 - cur;
    }
    if (t < NSCAN) g_blkoff[t] = sh[cur][t] - v;
}

__global__ __launch_bounds__(1024) void scan_blocks_kernel() {
    __shared__ int sh[2][1024];
    int gid = blockIdx.x * SCAN_CHUNK + threadIdx.x;
    int v = (gid < N_NODES) ? g_deg[gid] : 0;
    sh[0][threadIdx.x] = v;
    __syncthreads();
    int cur = 0;
#pragma unroll
    for (int o = 1; o < 1024; o <<= 1) {
        int y = sh[cur][threadIdx.x];
        if ((int)threadIdx.x >= o) y += sh[cur][threadIdx.x - o];
        sh[1 - cur][threadIdx.x] = y;
        __syncthreads();
        cur = 1 - cur;
    }
    int inc = sh[cur][threadIdx.x];
    int base = g_blkoff[blockIdx.x];
    if (gid < N_NODES) {
        int exc = base + inc - v;
        g_off[gid] = exc;
        g_cursor[gid] = exc;
        if (gid == N_NODES - 1) g_off[N_NODES] = base + inc;
    }
}

// ---------------------------------------------------------------------------
// combo_B: GEMM part 2 (LOW bid) || scalar CSR fill (1 edge/thread)
// ---------------------------------------------------------------------------
__global__ __launch_bounds__(256) void combo_b_kernel(
    const float* __restrict__ cf, const float* __restrict__ Wp,
    const float* __restrict__ bp, const float* __restrict__ wg,
    const float* __restrict__ bg, const float* __restrict__ item_emb,
    const int* __restrict__ src, const int* __restrict__ dst,
    const float* __restrict__ w) {
    const int bid = blockIdx.x;
    const int tid = threadIdx.x;
    if (bid < GEMM_B) {
        gemm_tile(GEMM_A + bid, cf, Wp, bp, wg, bg, item_emb);
        return;
    }
    int e = (bid - GEMM_B) * 256 + tid;
    if (e < N_EDGES) {
        int pos = atomicAdd(&g_cursor[dst[e]], 1);
        g_csr_src[pos] = src[e];
        g_csr_w[pos] = w[e];
    }
}

// ---------------------------------------------------------------------------
// fused layer: half-warp per node, float4 per lane
// ---------------------------------------------------------------------------
__global__ __launch_bounds__(256) void layer_kernel(int l) {
    const float4* ein;
    float4* eout;
    if (l == 0)      { ein = (const float4*)g_e0; eout = (float4*)g_e1; }
    else if (l == 1) { ein = (const float4*)g_e1; eout = (float4*)g_e2; }
    else             { ein = (const float4*)g_e2; eout = (float4*)g_e3; }

    int warp = threadIdx.x >> 5;
    int lane = threadIdx.x & 31;
    int half = lane >> 4;
    int l16  = lane & 15;
    int node = blockIdx.x * 16 + warp * 2 + half;
    if (node >= N_NODES) return;
    int beg = g_off[node];
    int end = g_off[node + 1];

    float ax = 0.f, ay = 0.f, az = 0.f, aw = 0.f;
    int i = beg;
    for (; i + 4 <= end; i += 4) {
        int s0 = g_csr_src[i + 0], s1 = g_csr_src[i + 1];
        int s2 = g_csr_src[i + 2], s3 = g_csr_src[i + 3];
        float4 x0 = ein[s0 * 16 + l16];
        float4 x1 = ein[s1 * 16 + l16];
        float4 x2 = ein[s2 * 16 + l16];
        float4 x3 = ein[s3 * 16 + l16];
        float w0 = g_csr_w[i + 0], w1 = g_csr_w[i + 1];
        float w2 = g_csr_w[i + 2], w3 = g_csr_w[i + 3];
        ax += w0 * x0.x; ay += w0 * x0.y; az += w0 * x0.z; aw += w0 * x0.w;
        ax += w1 * x1.x; ay += w1 * x1.y; az += w1 * x1.z; aw += w1 * x1.w;
        ax += w2 * x2.x; ay += w2 * x2.y; az += w2 * x2.z; aw += w2 * x2.w;
        ax += w3 * x3.x; ay += w3 * x3.y; az += w3 * x3.z; aw += w3 * x3.w;
    }
    for (; i < end; i++) {
        int s = g_csr_src[i];
        float wv = g_csr_w[i];
        float4 x = ein[s * 16 + l16];
        ax += wv * x.x; ay += wv * x.y; az += wv * x.z; aw += wv * x.w;
    }

    float s = ax + ay + az + aw;
#pragma unroll
    for (int o = 8; o; o >>= 1) s += __shfl_xor_sync(0xFFFFFFFFu, s, o);
    float m = s * (1.f / 64.f);
    float dx = ax - m, dy = ay - m, dz = az - m, dw = aw - m;
    float v = dx * dx + dy * dy + dz * dz + dw * dw;
#pragma unroll
    for (int o = 8; o; o >>= 1) v += __shfl_xor_sync(0xFFFFFFFFu, v, o);
    float rs = rsqrtf(v * (1.f / 64.f) + LN_EPS);

    float4 r = ein[node * 16 + l16];
    eout[node * 16 + l16] =
        make_float4(dx * rs + r.x, dy * rs + r.y, dz * rs + r.z, dw * rs + r.w);
}

// ---------------------------------------------------------------------------
// fused outputs
// ---------------------------------------------------------------------------
__global__ __launch_bounds__(256) void out_combo_kernel(
    const int* __restrict__ u, const int* __restrict__ p,
    const int* __restrict__ n, float* __restrict__ out) {
    const int bid = blockIdx.x;
    const int tid = threadIdx.x;

    if (bid < GATHER_BLOCKS) {
        int row  = bid * 4 + (tid >> 6);
        int d    = tid & 63;
        int which = row >> 12;
        int b     = row & 4095;
        int idx;
        if (which == 0)      idx = u[b];
        else if (which == 1) idx = N_USERS + p[b];
        else                 idx = N_USERS + n[b];
        long long o = (long long)idx * D + d;
        out[(long long)row * D + d] =
            (g_e0[o] + g_e1[o] + g_e2[o] + g_e3[o]) * 0.25f;
        return;
    }

    __shared__ float sh[256];
    int lb = bid - GATHER_BLOCKS;
    int i = lb * 256 + tid;
    const float4* e0 = (const float4*)(g_e0 + (long long)N_USERS * D);
    const float4* e1 = (const float4*)(g_e1 + (long long)N_USERS * D);
    const float4* e2 = (const float4*)(g_e2 + (long long)N_USERS * D);
    const float4* e3 = (const float4*)(g_e3 + (long long)N_USERS * D);
    const float4* ic = (const float4*)g_ic;
    float4 a = e0[i], b = e1[i], c = e2[i], d4 = e3[i], f = ic[i];
    float dx = (a.x + b.x + c.x + d4.x) * 0.25f - f.x;
    float dy = (a.y + b.y + c.y + d4.y) * 0.25f - f.y;
    float dz = (a.z + b.z + c.z + d4.z) * 0.25f - f.z;
    float dw = (a.w + b.w + c.w + d4.w) * 0.25f - f.w;
    sh[tid] = dx * dx + dy * dy + dz * dz + dw * dw;
    __syncthreads();
#pragma unroll
    for (int o = 128; o; o >>= 1) {
        if (tid < o) sh[tid] += sh[tid + o];
        __syncthreads();
    }
    if (tid == 0) g_partials[lb] = sh[0];
}

__global__ __launch_bounds__(1024) void loss_final_kernel(float* __restrict__ out) {
    __shared__ float sh[1024];
    float s = 0.f;
    for (int i = threadIdx.x; i < LOSS_BLOCKS; i += 1024) s += g_partials[i];
    sh[threadIdx.x] = s;
    __syncthreads();
#pragma unroll
    for (int o = 512; o; o >>= 1) {
        if (threadIdx.x < o) sh[threadIdx.x] += sh[threadIdx.x + o];
        __syncthreads();
    }
    if (threadIdx.x == 0)
        out[3 * BATCH * D] = sh[0] * (0.1f / (float)(N_ITEMS * D));
}

// ---------------------------------------------------------------------------
extern "C" void kernel_launch(void* const* d_in, const int* in_sizes, int n_in,
                              void* d_out, int out_size) {
    const int*   users     = (const int*)  d_in[0];
    const int*   pos_items = (const int*)  d_in[1];
    const int*   neg_items = (const int*)  d_in[2];
    const int*   edge_src  = (const int*)  d_in[3];
    const int*   edge_dst  = (const int*)  d_in[4];
    const float* edge_w    = (const float*)d_in[5];
    const float* user_emb  = (const float*)d_in[6];
    const float* item_emb  = (const float*)d_in[7];
    const float* cf        = (const float*)d_in[8];
    const float* Wp        = (const float*)d_in[9];
    const float* bp        = (const float*)d_in[10];
    const float* wg        = (const float*)d_in[11];
    const float* bg        = (const float*)d_in[12];
    float* out = (float*)d_out;

    zero_deg_kernel<<<(N_NODES + 255) / 256, 256>>>();
    combo_a_kernel<<<COMBO_A_BLOCKS, 256>>>(cf, Wp, bp, wg, bg, item_emb,
                                            user_emb, (const int4*)edge_dst);
    scan_sum_kernel<<<NSCAN, 1024>>>();
    scan_top_kernel<<<1, 256>>>();
    scan_blocks_kernel<<<NSCAN, 1024>>>();
    combo_b_kernel<<<COMBO_B_BLOCKS, 256>>>(cf, Wp, bp, wg, bg, item_emb,
                                            edge_src, edge_dst, edge_w);

    const int ln_blocks = (N_NODES + 15) / 16;
    layer_kernel<<<ln_blocks, 256>>>(0);
    layer_kernel<<<ln_blocks, 256>>>(1);
    layer_kernel<<<ln_blocks, 256>>>(2);

    out_combo_kernel<<<OUT_BLOCKS, 256>>>(users, pos_items, neg_items, out);
    loss_final_kernel<<<1, 1024>>>(out);
}

// round 11
// speedup vs baseline: 1.0701x; 1.0701x over previous
#include <cuda_runtime.h>
#include <cuda_bf16.h>

#define N_USERS 100000
#define N_ITEMS 50000
#define N_NODES (N_USERS + N_ITEMS)
#define D 64
#define F 768
#define N_EDGES 4800000
#define BATCH 4096
#define LN_EPS 1e-5f

#define SCAN_CHUNK 1024
#define NSCAN ((N_NODES + SCAN_CHUNK - 1) / SCAN_CHUNK)   // 147

#define GEMM_BLOCKS ((N_ITEMS + 63) / 64)                 // 782
#define FILL_BLOCKS ((N_EDGES + 255) / 256)               // 18750
#define INIT_BLOCKS 1024
#define COMBO_BLOCKS (GEMM_BLOCKS + FILL_BLOCKS + INIT_BLOCKS)

#define GATHER_BLOCKS (3 * BATCH / 4)                     // 3072
#define LOSS_BLOCKS (N_ITEMS * D / 4 / 256)               // 3125 exact
#define OUT_BLOCKS (GATHER_BLOCKS + LOSS_BLOCKS)

// ---- scratch (device globals) ----
__device__ float g_e0[N_NODES * D];
__device__ float g_e1[N_NODES * D];
__device__ float g_e2[N_NODES * D];
__device__ float g_e3[N_NODES * D];
__device__ float g_ic[N_ITEMS * D];
__device__ int   g_deg[N_NODES];
__device__ int   g_off[N_NODES + 1];
__device__ int   g_cursor[N_NODES];
__device__ int   g_blksum[NSCAN];
__device__ int   g_csr_src[N_EDGES];
__device__ float g_csr_w[N_EDGES];
__device__ float g_partials[LOSS_BLOCKS];
__device__ int   g_scan_done;
__device__ int   g_loss_done;

// packed f32x2 FMA (sm_103a FFMA2 — exact fp32)
__device__ __forceinline__ unsigned long long pack2(float lo, float hi) {
    unsigned long long r;
    asm("mov.b64 %0, {%1, %2};" : "=l"(r) : "f"(lo), "f"(hi));
    return r;
}
__device__ __forceinline__ void ffma2(unsigned long long& a,
                                      unsigned long long c,
                                      unsigned long long b) {
    asm("fma.rn.f32x2 %0, %1, %2, %0;" : "+l"(a) : "l"(c), "l"(b));
}
__device__ __forceinline__ float2 unpack2(unsigned long long v) {
    float2 r;
    asm("mov.b64 {%0, %1}, %2;" : "=f"(r.x), "=f"(r.y) : "l"(v));
    return r;
}

// ---------------------------------------------------------------------------
// zero degrees + reset spin counters (replay-safe)
// ---------------------------------------------------------------------------
__global__ void zero_deg_kernel() {
    int i = blockIdx.x * blockDim.x + threadIdx.x;
    if (i < N_NODES) g_deg[i] = 0;
    if (i == 0) { g_scan_done = 0; g_loss_done = 0; }
}

__global__ void hist_kernel(const int4* __restrict__ dst4) {
    int i = blockIdx.x * blockDim.x + threadIdx.x;
    if (i < N_EDGES / 4) {
        int4 d = dst4[i];
        atomicAdd(&g_deg[d.x], 1);
        atomicAdd(&g_deg[d.y], 1);
        atomicAdd(&g_deg[d.z], 1);
        atomicAdd(&g_deg[d.w], 1);
    }
}

// ---------------------------------------------------------------------------
// fused scan: per-block inclusive scan + global spin barrier + base add.
// 147 blocks x 1024 threads -> all co-resident (296 slots) => spin is safe.
// ---------------------------------------------------------------------------
__global__ __launch_bounds__(1024) void scan_fused_kernel() {
    __shared__ int sh[2][1024];
    int t = threadIdx.x;
    int gid = blockIdx.x * SCAN_CHUNK + t;
    int v = (gid < N_NODES) ? g_deg[gid] : 0;

    // inclusive scan within block
    sh[0][t] = v;
    __syncthreads();
    int cur = 0;
#pragma unroll
    for (int o = 1; o < 1024; o <<= 1) {
        int y = sh[cur][t];
        if (t >= o) y += sh[cur][t - o];
        sh[1 - cur][t] = y;
        __syncthreads();
        cur = 1 - cur;
    }
    int inc = sh[cur][t];

    // publish block total, arrive
    if (t == 1023) {
        g_blksum[blockIdx.x] = inc;   // t==1023 holds the block total
        __threadfence();
        atomicAdd(&g_scan_done, 1);
    }
    // spin until all block totals published
    if (t == 0) {
        while (*(volatile int*)&g_scan_done < NSCAN) { }
    }
    __syncthreads();
    __threadfence();

    // base = sum of blksum[j] for j < blockIdx.x  (parallel reduce)
    int b = (t < blockIdx.x) ? ((volatile int*)g_blksum)[t] : 0;  // NSCAN<=1024
    __syncthreads();          // sh reuse safe: inc in registers
    sh[0][t] = b;
    __syncthreads();
#pragma unroll
    for (int o = 512; o; o >>= 1) {
        if (t < o) sh[0][t] += sh[0][t + o];
        __syncthreads();
    }
    int base = sh[0][0];

    if (gid < N_NODES) {
        int exc = base + inc - v;
        g_off[gid] = exc;
        g_cursor[gid] = exc;
        if (gid == N_NODES - 1) g_off[N_NODES] = base + inc;
    }
}

// ---------------------------------------------------------------------------
// combo (R9 winner): GEMM (FFMA2, low bid) || scalar CSR fill || user init
// ---------------------------------------------------------------------------
__global__ __launch_bounds__(256) void combo_kernel(
    const float* __restrict__ cf, const float* __restrict__ Wp,
    const float* __restrict__ bp, const float* __restrict__ wg,
    const float* __restrict__ bg, const float* __restrict__ item_emb,
    const float* __restrict__ user_emb,
    const int* __restrict__ src, const int* __restrict__ dst,
    const float* __restrict__ w) {

    __shared__ float Cs[32][68];
    __shared__ float Ws[32][64];
    __shared__ float wgs[32];
    __shared__ float gates[64];

    const int bid = blockIdx.x;
    const int tid = threadIdx.x;

    if (bid >= GEMM_BLOCKS) {
        int b2 = bid - GEMM_BLOCKS;
        if (b2 < FILL_BLOCKS) {
            int e = b2 * 256 + tid;
            if (e < N_EDGES) {
                int pos = atomicAdd(&g_cursor[dst[e]], 1);
                g_csr_src[pos] = src[e];
                g_csr_w[pos] = w[e];
            }
        } else {
            int b3 = b2 - FILL_BLOCKS;
            const int n = N_USERS * D / 4;
            const float4* u4 = (const float4*)user_emb;
            float4* e4 = (float4*)g_e0;
            for (int i = b3 * 256 + tid; i < n; i += INIT_BLOCKS * 256)
                e4[i] = u4[i];
        }
        return;
    }

    const int d     = tid & 63;
    const int r     = tid >> 6;
    const int item0 = bid * 64;

    unsigned long long acc2[8];
#pragma unroll
    for (int i = 0; i < 8; i++) acc2[i] = 0ull;
    float gp = 0.f;

    for (int kt = 0; kt < F; kt += 32) {
#pragma unroll
        for (int j = 0; j < 8; j++) {
            int l = tid + j * 256;
            int it = l >> 5, k = l & 31;
            int item = item0 + it;
            Cs[k][it] = (item < N_ITEMS) ? cf[item * F + kt + k] : 0.f;
        }
#pragma unroll
        for (int j = 0; j < 8; j++) {
            int l = tid + j * 256;
            int k = l >> 6, dd = l & 63;
            Ws[k][dd] = Wp[(kt + k) * D + dd];
        }
        if (tid < 32) wgs[tid] = wg[kt + tid];
        __syncthreads();

        if (tid < 64) {
#pragma unroll
            for (int k = 0; k < 32; k++) gp += Cs[k][tid] * wgs[k];
        }
#pragma unroll
        for (int k = 0; k < 32; k++) {
            float wv = Ws[k][d];
            unsigned long long w2 = pack2(wv, wv);
            const ulonglong2* cp = (const ulonglong2*)&Cs[k][r * 16];
#pragma unroll
            for (int q = 0; q < 4; q++) {
                ulonglong2 c = cp[q];
                ffma2(acc2[q * 2 + 0], c.x, w2);
                ffma2(acc2[q * 2 + 1], c.y, w2);
            }
        }
        __syncthreads();
    }

    if (tid < 64) gates[tid] = 1.f / (1.f + expf(-(gp + bg[0])));
    __syncthreads();

    const float bpd = bp[d];
#pragma unroll
    for (int p = 0; p < 8; p++) {
        float2 a = unpack2(acc2[p]);
#pragma unroll
        for (int h = 0; h < 2; h++) {
            int it = p * 2 + h;
            int item = item0 + r * 16 + it;
            if (item < N_ITEMS) {
                float ic = (h ? a.y : a.x) + bpd;
                g_ic[item * D + d] = ic;
                float g = gates[r * 16 + it];
                g_e0[(N_USERS + item) * D + d] =
                    (1.f - g) * item_emb[item * D + d] + g * ic;
            }
        }
    }
}

// ---------------------------------------------------------------------------
// fused layer: half-warp per node, float4 per lane
// ---------------------------------------------------------------------------
__global__ __launch_bounds__(256) void layer_kernel(int l) {
    const float4* ein;
    float4* eout;
    if (l == 0)      { ein = (const float4*)g_e0; eout = (float4*)g_e1; }
    else if (l == 1) { ein = (const float4*)g_e1; eout = (float4*)g_e2; }
    else             { ein = (const float4*)g_e2; eout = (float4*)g_e3; }

    int warp = threadIdx.x >> 5;
    int lane = threadIdx.x & 31;
    int half = lane >> 4;
    int l16  = lane & 15;
    int node = blockIdx.x * 16 + warp * 2 + half;
    if (node >= N_NODES) return;
    int beg = g_off[node];
    int end = g_off[node + 1];

    float ax = 0.f, ay = 0.f, az = 0.f, aw = 0.f;
    int i = beg;
    for (; i + 4 <= end; i += 4) {
        int s0 = g_csr_src[i + 0], s1 = g_csr_src[i + 1];
        int s2 = g_csr_src[i + 2], s3 = g_csr_src[i + 3];
        float4 x0 = ein[s0 * 16 + l16];
        float4 x1 = ein[s1 * 16 + l16];
        float4 x2 = ein[s2 * 16 + l16];
        float4 x3 = ein[s3 * 16 + l16];
        float w0 = g_csr_w[i + 0], w1 = g_csr_w[i + 1];
        float w2 = g_csr_w[i + 2], w3 = g_csr_w[i + 3];
        ax += w0 * x0.x; ay += w0 * x0.y; az += w0 * x0.z; aw += w0 * x0.w;
        ax += w1 * x1.x; ay += w1 * x1.y; az += w1 * x1.z; aw += w1 * x1.w;
        ax += w2 * x2.x; ay += w2 * x2.y; az += w2 * x2.z; aw += w2 * x2.w;
        ax += w3 * x3.x; ay += w3 * x3.y; az += w3 * x3.z; aw += w3 * x3.w;
    }
    for (; i < end; i++) {
        int s = g_csr_src[i];
        float wv = g_csr_w[i];
        float4 x = ein[s * 16 + l16];
        ax += wv * x.x; ay += wv * x.y; az += wv * x.z; aw += wv * x.w;
    }

    float s = ax + ay + az + aw;
#pragma unroll
    for (int o = 8; o; o >>= 1) s += __shfl_xor_sync(0xFFFFFFFFu, s, o);
    float m = s * (1.f / 64.f);
    float dx = ax - m, dy = ay - m, dz = az - m, dw = aw - m;
    float v = dx * dx + dy * dy + dz * dz + dw * dw;
#pragma unroll
    for (int o = 8; o; o >>= 1) v += __shfl_xor_sync(0xFFFFFFFFu, v, o);
    float rs = rsqrtf(v * (1.f / 64.f) + LN_EPS);

    float4 r = ein[node * 16 + l16];
    eout[node * 16 + l16] =
        make_float4(dx * rs + r.x, dy * rs + r.y, dz * rs + r.z, dw * rs + r.w);
}

// ---------------------------------------------------------------------------
// fused outputs: gathers + loss partials + last-block final loss reduce
// ---------------------------------------------------------------------------
__global__ __launch_bounds__(256) void out_combo_kernel(
    const int* __restrict__ u, const int* __restrict__ p,
    const int* __restrict__ n, float* __restrict__ out) {
    const int bid = blockIdx.x;
    const int tid = threadIdx.x;

    if (bid < GATHER_BLOCKS) {
        int row  = bid * 4 + (tid >> 6);
        int d    = tid & 63;
        int which = row >> 12;
        int b     = row & 4095;
        int idx;
        if (which == 0)      idx = u[b];
        else if (which == 1) idx = N_USERS + p[b];
        else                 idx = N_USERS + n[b];
        long long o = (long long)idx * D + d;
        out[(long long)row * D + d] =
            (g_e0[o] + g_e1[o] + g_e2[o] + g_e3[o]) * 0.25f;
        return;
    }

    __shared__ float sh[256];
    __shared__ int s_last;
    int lb = bid - GATHER_BLOCKS;
    int i = lb * 256 + tid;
    const float4* e0 = (const float4*)(g_e0 + (long long)N_USERS * D);
    const float4* e1 = (const float4*)(g_e1 + (long long)N_USERS * D);
    const float4* e2 = (const float4*)(g_e2 + (long long)N_USERS * D);
    const float4* e3 = (const float4*)(g_e3 + (long long)N_USERS * D);
    const float4* ic = (const float4*)g_ic;
    float4 a = e0[i], b = e1[i], c = e2[i], d4 = e3[i], f = ic[i];
    float dx = (a.x + b.x + c.x + d4.x) * 0.25f - f.x;
    float dy = (a.y + b.y + c.y + d4.y) * 0.25f - f.y;
    float dz = (a.z + b.z + c.z + d4.z) * 0.25f - f.z;
    float dw = (a.w + b.w + c.w + d4.w) * 0.25f - f.w;
    sh[tid] = dx * dx + dy * dy + dz * dz + dw * dw;
    __syncthreads();
#pragma unroll
    for (int o = 128; o; o >>= 1) {
        if (tid < o) sh[tid] += sh[tid + o];
        __syncthreads();
    }
    if (tid == 0) {
        g_partials[lb] = sh[0];
        __threadfence();
        int done = atomicAdd(&g_loss_done, 1);
        s_last = (done == LOSS_BLOCKS - 1) ? 1 : 0;
    }
    __syncthreads();

    // last-finishing loss block reduces all partials (fixed order -> deterministic)
    if (s_last) {
        __threadfence();
        float s = 0.f;
        for (int j = tid; j < LOSS_BLOCKS; j += 256)
            s += ((volatile float*)g_partials)[j];
        sh[tid] = s;
        __syncthreads();
#pragma unroll
        for (int o = 128; o; o >>= 1) {
            if (tid < o) sh[tid] += sh[tid + o];
            __syncthreads();
        }
        if (tid == 0)
            out[3 * BATCH * D] = sh[0] * (0.1f / (float)(N_ITEMS * D));
    }
}

// ---------------------------------------------------------------------------
extern "C" void kernel_launch(void* const* d_in, const int* in_sizes, int n_in,
                              void* d_out, int out_size) {
    const int*   users     = (const int*)  d_in[0];
    const int*   pos_items = (const int*)  d_in[1];
    const int*   neg_items = (const int*)  d_in[2];
    const int*   edge_src  = (const int*)  d_in[3];
    const int*   edge_dst  = (const int*)  d_in[4];
    const float* edge_w    = (const float*)d_in[5];
    const float* user_emb  = (const float*)d_in[6];
    const float* item_emb  = (const float*)d_in[7];
    const float* cf        = (const float*)d_in[8];
    const float* Wp        = (const float*)d_in[9];
    const float* bp        = (const float*)d_in[10];
    const float* wg        = (const float*)d_in[11];
    const float* bg        = (const float*)d_in[12];
    float* out = (float*)d_out;

    zero_deg_kernel<<<(N_NODES + 255) / 256, 256>>>();
    hist_kernel<<<(N_EDGES / 4 + 255) / 256, 256>>>((const int4*)edge_dst);
    scan_fused_kernel<<<NSCAN, 1024>>>();

    combo_kernel<<<COMBO_BLOCKS, 256>>>(cf, Wp, bp, wg, bg, item_emb,
                                        user_emb, edge_src, edge_dst, edge_w);

    const int ln_blocks = (N_NODES + 15) / 16;
    layer_kernel<<<ln_blocks, 256>>>(0);
    layer_kernel<<<ln_blocks, 256>>>(1);
    layer_kernel<<<ln_blocks, 256>>>(2);

    out_combo_kernel<<<OUT_BLOCKS, 256>>>(users, pos_items, neg_items, out);
}

// round 13
// speedup vs baseline: 1.1512x; 1.0758x over previous
#include <cuda_runtime.h>
#include <cuda_bf16.h>

#define N_USERS 100000
#define N_ITEMS 50000
#define N_NODES (N_USERS + N_ITEMS)
#define D 64
#define F 768
#define N_EDGES 4800000
#define BATCH 4096
#define LN_EPS 1e-5f

#define SCAN_CHUNK 1024
#define NSCAN ((N_NODES + SCAN_CHUNK - 1) / SCAN_CHUNK)   // 147

#define GEMM_BLOCKS ((N_ITEMS + 63) / 64)                 // 782
#define FILL_BLOCKS ((N_EDGES + 255) / 256)               // 18750
#define INIT_BLOCKS 1024
#define COMBO_BLOCKS (GEMM_BLOCKS + FILL_BLOCKS + INIT_BLOCKS)

#define KTILES (F / 32)                                   // 24

#define GATHER_BLOCKS (3 * BATCH / 4)                     // 3072
#define LOSS_BLOCKS (N_ITEMS * D / 4 / 256)               // 3125 exact
#define OUT_BLOCKS (GATHER_BLOCKS + LOSS_BLOCKS)

// ---- scratch (device globals) ----
__device__ float g_e0[N_NODES * D];
__device__ float g_e1[N_NODES * D];
__device__ float g_e2[N_NODES * D];
__device__ float g_e3[N_NODES * D];
__device__ float g_ic[N_ITEMS * D];
__device__ int   g_deg[N_NODES];
__device__ int   g_off[N_NODES + 1];
__device__ int   g_cursor[N_NODES];
__device__ int   g_blksum[NSCAN];
__device__ int   g_csr_src[N_EDGES];
__device__ float g_csr_w[N_EDGES];
__device__ float g_partials[LOSS_BLOCKS];
__device__ int   g_scan_done;
__device__ int   g_loss_done;

// packed f32x2 FMA (sm_103a FFMA2 — exact fp32)
__device__ __forceinline__ unsigned long long pack2(float lo, float hi) {
    unsigned long long r;
    asm("mov.b64 %0, {%1, %2};" : "=l"(r) : "f"(lo), "f"(hi));
    return r;
}
__device__ __forceinline__ void ffma2(unsigned long long& a,
                                      unsigned long long c,
                                      unsigned long long b) {
    asm("fma.rn.f32x2 %0, %1, %2, %0;" : "+l"(a) : "l"(c), "l"(b));
}
__device__ __forceinline__ float2 unpack2(unsigned long long v) {
    float2 r;
    asm("mov.b64 {%0, %1}, %2;" : "=f"(r.x), "=f"(r.y) : "l"(v));
    return r;
}

// ---------------------------------------------------------------------------
__global__ void zero_deg_kernel() {
    int i = blockIdx.x * blockDim.x + threadIdx.x;
    if (i < N_NODES) g_deg[i] = 0;
    if (i == 0) { g_scan_done = 0; g_loss_done = 0; }
}

__global__ void hist_kernel(const int4* __restrict__ dst4) {
    int i = blockIdx.x * blockDim.x + threadIdx.x;
    if (i < N_EDGES / 4) {
        int4 d = dst4[i];
        atomicAdd(&g_deg[d.x], 1);
        atomicAdd(&g_deg[d.y], 1);
        atomicAdd(&g_deg[d.z], 1);
        atomicAdd(&g_deg[d.w], 1);
    }
}

// ---------------------------------------------------------------------------
// fused scan (all 147 blocks co-resident -> spin barrier is safe)
// ---------------------------------------------------------------------------
__global__ __launch_bounds__(1024) void scan_fused_kernel() {
    __shared__ int sh[2][1024];
    int t = threadIdx.x;
    int gid = blockIdx.x * SCAN_CHUNK + t;
    int v = (gid < N_NODES) ? g_deg[gid] : 0;

    sh[0][t] = v;
    __syncthreads();
    int cur = 0;
#pragma unroll
    for (int o = 1; o < 1024; o <<= 1) {
        int y = sh[cur][t];
        if (t >= o) y += sh[cur][t - o];
        sh[1 - cur][t] = y;
        __syncthreads();
        cur = 1 - cur;
    }
    int inc = sh[cur][t];

    if (t == 1023) {
        g_blksum[blockIdx.x] = inc;
        __threadfence();
        atomicAdd(&g_scan_done, 1);
    }
    if (t == 0) {
        while (*(volatile int*)&g_scan_done < NSCAN) { }
    }
    __syncthreads();
    __threadfence();

    int b = (t < blockIdx.x) ? ((volatile int*)g_blksum)[t] : 0;
    __syncthreads();
    sh[0][t] = b;
    __syncthreads();
#pragma unroll
    for (int o = 512; o; o >>= 1) {
        if (t < o) sh[0][t] += sh[0][t + o];
        __syncthreads();
    }
    int base = sh[0][0];

    if (gid < N_NODES) {
        int exc = base + inc - v;
        g_off[gid] = exc;
        g_cursor[gid] = exc;
        if (gid == N_NODES - 1) g_off[N_NODES] = base + inc;
    }
}

// ---------------------------------------------------------------------------
// combo: GEMM (double-buffered Cs, W via L1 global) || scalar fill || init
// ---------------------------------------------------------------------------
__global__ __launch_bounds__(256, 4) void combo_kernel(
    const float* __restrict__ cf, const float* __restrict__ Wp,
    const float* __restrict__ bp, const float* __restrict__ wg,
    const float* __restrict__ bg, const float* __restrict__ item_emb,
    const float* __restrict__ user_emb,
    const int* __restrict__ src, const int* __restrict__ dst,
    const float* __restrict__ w) {

    __shared__ float Cs[2][32][68];   // double-buffered [k][item]
    __shared__ float gates[64];

    const int bid = blockIdx.x;
    const int tid = threadIdx.x;

    if (bid >= GEMM_BLOCKS) {
        int b2 = bid - GEMM_BLOCKS;
        if (b2 < FILL_BLOCKS) {
            int e = b2 * 256 + tid;
            if (e < N_EDGES) {
                int pos = atomicAdd(&g_cursor[dst[e]], 1);
                g_csr_src[pos] = src[e];
                g_csr_w[pos] = w[e];
            }
        } else {
            int b3 = b2 - FILL_BLOCKS;
            const int n = N_USERS * D / 4;
            const float4* u4 = (const float4*)user_emb;
            float4* e4 = (float4*)g_e0;
            for (int i = b3 * 256 + tid; i < n; i += INIT_BLOCKS * 256)
                e4[i] = u4[i];
        }
        return;
    }

    // ---- fused item GEMM + gate + mix ----
    const int d     = tid & 63;
    const int r     = tid >> 6;
    const int item0 = bid * 64;

    // staging map: thread (tid, j) covers item row it_l + j*8, k = k_l
    // ((tid + j*256) >> 5 == tid>>5 + j*8 — R12's bug was j*32 here)
    const int it_l = tid >> 5;        // 0..7
    const int k_l  = tid & 31;

    unsigned long long acc2[8];
#pragma unroll
    for (int i = 0; i < 8; i++) acc2[i] = 0ull;
    float gp = 0.f;

    // prologue: stage tile 0
#pragma unroll
    for (int j = 0; j < 8; j++) {
        int it = it_l + j * 8;                 // 0..63
        int item = item0 + it;
        Cs[0][k_l][it] = (item < N_ITEMS) ? cf[item * F + k_l] : 0.f;
    }
    __syncthreads();

    for (int kt = 0; kt < KTILES; kt++) {
        int cur = kt & 1;
        // prefetch next tile into the other buffer
        if (kt + 1 < KTILES) {
            int kbase = (kt + 1) * 32;
#pragma unroll
            for (int j = 0; j < 8; j++) {
                int it = it_l + j * 8;
                int item = item0 + it;
                Cs[1 - cur][k_l][it] =
                    (item < N_ITEMS) ? cf[item * F + kbase + k_l] : 0.f;
            }
        }

        // gate partial (threads 0..63) — wg from global L1
        if (tid < 64) {
#pragma unroll
            for (int k = 0; k < 32; k++)
                gp += Cs[cur][k][tid] * __ldg(&wg[kt * 32 + k]);
        }

        // main FFMA2 loop — Wp straight from global (L1-hot, coalesced)
        const float* wcol = Wp + (kt * 32) * D + d;
#pragma unroll
        for (int k = 0; k < 32; k++) {
            float wv = __ldg(wcol + k * D);
            unsigned long long w2 = pack2(wv, wv);
            const ulonglong2* cp = (const ulonglong2*)&Cs[cur][k][r * 16];
#pragma unroll
            for (int q = 0; q < 4; q++) {
                ulonglong2 c = cp[q];
                ffma2(acc2[q * 2 + 0], c.x, w2);
                ffma2(acc2[q * 2 + 1], c.y, w2);
            }
        }
        __syncthreads();   // next buffer staged + current free for kt+2
    }

    if (tid < 64) gates[tid] = 1.f / (1.f + expf(-(gp + bg[0])));
    __syncthreads();

    const float bpd = bp[d];
#pragma unroll
    for (int p = 0; p < 8; p++) {
        float2 a = unpack2(acc2[p]);
#pragma unroll
        for (int h = 0; h < 2; h++) {
            int it = p * 2 + h;
            int item = item0 + r * 16 + it;
            if (item < N_ITEMS) {
                float ic = (h ? a.y : a.x) + bpd;
                g_ic[item * D + d] = ic;
                float g = gates[r * 16 + it];
                g_e0[(N_USERS + item) * D + d] =
                    (1.f - g) * item_emb[item * D + d] + g * ic;
            }
        }
    }
}

// ---------------------------------------------------------------------------
// fused layer: half-warp per node, float4 per lane
// ---------------------------------------------------------------------------
__global__ __launch_bounds__(256) void layer_kernel(int l) {
    const float4* ein;
    float4* eout;
    if (l == 0)      { ein = (const float4*)g_e0; eout = (float4*)g_e1; }
    else if (l == 1) { ein = (const float4*)g_e1; eout = (float4*)g_e2; }
    else             { ein = (const float4*)g_e2; eout = (float4*)g_e3; }

    int warp = threadIdx.x >> 5;
    int lane = threadIdx.x & 31;
    int half = lane >> 4;
    int l16  = lane & 15;
    int node = blockIdx.x * 16 + warp * 2 + half;
    if (node >= N_NODES) return;
    int beg = g_off[node];
    int end = g_off[node + 1];

    float ax = 0.f, ay = 0.f, az = 0.f, aw = 0.f;
    int i = beg;
    for (; i + 4 <= end; i += 4) {
        int s0 = g_csr_src[i + 0], s1 = g_csr_src[i + 1];
        int s2 = g_csr_src[i + 2], s3 = g_csr_src[i + 3];
        float4 x0 = ein[s0 * 16 + l16];
        float4 x1 = ein[s1 * 16 + l16];
        float4 x2 = ein[s2 * 16 + l16];
        float4 x3 = ein[s3 * 16 + l16];
        float w0 = g_csr_w[i + 0], w1 = g_csr_w[i + 1];
        float w2 = g_csr_w[i + 2], w3 = g_csr_w[i + 3];
        ax += w0 * x0.x; ay += w0 * x0.y; az += w0 * x0.z; aw += w0 * x0.w;
        ax += w1 * x1.x; ay += w1 * x1.y; az += w1 * x1.z; aw += w1 * x1.w;
        ax += w2 * x2.x; ay += w2 * x2.y; az += w2 * x2.z; aw += w2 * x2.w;
        ax += w3 * x3.x; ay += w3 * x3.y; az += w3 * x3.z; aw += w3 * x3.w;
    }
    for (; i < end; i++) {
        int s = g_csr_src[i];
        float wv = g_csr_w[i];
        float4 x = ein[s * 16 + l16];
        ax += wv * x.x; ay += wv * x.y; az += wv * x.z; aw += wv * x.w;
    }

    float s = ax + ay + az + aw;
#pragma unroll
    for (int o = 8; o; o >>= 1) s += __shfl_xor_sync(0xFFFFFFFFu, s, o);
    float m = s * (1.f / 64.f);
    float dx = ax - m, dy = ay - m, dz = az - m, dw = aw - m;
    float v = dx * dx + dy * dy + dz * dz + dw * dw;
#pragma unroll
    for (int o = 8; o; o >>= 1) v += __shfl_xor_sync(0xFFFFFFFFu, v, o);
    float rs = rsqrtf(v * (1.f / 64.f) + LN_EPS);

    float4 r = ein[node * 16 + l16];
    eout[node * 16 + l16] =
        make_float4(dx * rs + r.x, dy * rs + r.y, dz * rs + r.z, dw * rs + r.w);
}

// ---------------------------------------------------------------------------
// fused outputs: gathers + loss partials + last-block final reduce
// ---------------------------------------------------------------------------
__global__ __launch_bounds__(256) void out_combo_kernel(
    const int* __restrict__ u, const int* __restrict__ p,
    const int* __restrict__ n, float* __restrict__ out) {
    const int bid = blockIdx.x;
    const int tid = threadIdx.x;

    if (bid < GATHER_BLOCKS) {
        int row  = bid * 4 + (tid >> 6);
        int d    = tid & 63;
        int which = row >> 12;
        int b     = row & 4095;
        int idx;
        if (which == 0)      idx = u[b];
        else if (which == 1) idx = N_USERS + p[b];
        else                 idx = N_USERS + n[b];
        long long o = (long long)idx * D + d;
        out[(long long)row * D + d] =
            (g_e0[o] + g_e1[o] + g_e2[o] + g_e3[o]) * 0.25f;
        return;
    }

    __shared__ float sh[256];
    __shared__ int s_last;
    int lb = bid - GATHER_BLOCKS;
    int i = lb * 256 + tid;
    const float4* e0 = (const float4*)(g_e0 + (long long)N_USERS * D);
    const float4* e1 = (const float4*)(g_e1 + (long long)N_USERS * D);
    const float4* e2 = (const float4*)(g_e2 + (long long)N_USERS * D);
    const float4* e3 = (const float4*)(g_e3 + (long long)N_USERS * D);
    const float4* ic = (const float4*)g_ic;
    float4 a = e0[i], b = e1[i], c = e2[i], d4 = e3[i], f = ic[i];
    float dx = (a.x + b.x + c.x + d4.x) * 0.25f - f.x;
    float dy = (a.y + b.y + c.y + d4.y) * 0.25f - f.y;
    float dz = (a.z + b.z + c.z + d4.z) * 0.25f - f.z;
    float dw = (a.w + b.w + c.w + d4.w) * 0.25f - f.w;
    sh[tid] = dx * dx + dy * dy + dz * dz + dw * dw;
    __syncthreads();
#pragma unroll
    for (int o = 128; o; o >>= 1) {
        if (tid < o) sh[tid] += sh[tid + o];
        __syncthreads();
    }
    if (tid == 0) {
        g_partials[lb] = sh[0];
        __threadfence();
        int done = atomicAdd(&g_loss_done, 1);
        s_last = (done == LOSS_BLOCKS - 1) ? 1 : 0;
    }
    __syncthreads();

    if (s_last) {
        __threadfence();
        float s = 0.f;
        for (int j = tid; j < LOSS_BLOCKS; j += 256)
            s += ((volatile float*)g_partials)[j];
        sh[tid] = s;
        __syncthreads();
#pragma unroll
        for (int o = 128; o; o >>= 1) {
            if (tid < o) sh[tid] += sh[tid + o];
            __syncthreads();
        }
        if (tid == 0)
            out[3 * BATCH * D] = sh[0] * (0.1f / (float)(N_ITEMS * D));
    }
}

// ---------------------------------------------------------------------------
extern "C" void kernel_launch(void* const* d_in, const int* in_sizes, int n_in,
                              void* d_out, int out_size) {
    const int*   users     = (const int*)  d_in[0];
    const int*   pos_items = (const int*)  d_in[1];
    const int*   neg_items = (const int*)  d_in[2];
    const int*   edge_src  = (const int*)  d_in[3];
    const int*   edge_dst  = (const int*)  d_in[4];
    const float* edge_w    = (const float*)d_in[5];
    const float* user_emb  = (const float*)d_in[6];
    const float* item_emb  = (const float*)d_in[7];
    const float* cf        = (const float*)d_in[8];
    const float* Wp        = (const float*)d_in[9];
    const float* bp        = (const float*)d_in[10];
    const float* wg        = (const float*)d_in[11];
    const float* bg        = (const float*)d_in[12];
    float* out = (float*)d_out;

    zero_deg_kernel<<<(N_NODES + 255) / 256, 256>>>();
    hist_kernel<<<(N_EDGES / 4 + 255) / 256, 256>>>((const int4*)edge_dst);
    scan_fused_kernel<<<NSCAN, 1024>>>();

    combo_kernel<<<COMBO_BLOCKS, 256>>>(cf, Wp, bp, wg, bg, item_emb,
                                        user_emb, edge_src, edge_dst, edge_w);

    const int ln_blocks = (N_NODES + 15) / 16;
    layer_kernel<<<ln_blocks, 256>>>(0);
    layer_kernel<<<ln_blocks, 256>>>(1);
    layer_kernel<<<ln_blocks, 256>>>(2);

    out_combo_kernel<<<OUT_BLOCKS, 256>>>(users, pos_items, neg_items, out);
}

// round 14
// speedup vs baseline: 1.2226x; 1.0620x over previous
#include <cuda_runtime.h>
#include <cuda_bf16.h>

#define N_USERS 100000
#define N_ITEMS 50000
#define N_NODES (N_USERS + N_ITEMS)
#define D 64
#define F 768
#define N_EDGES 4800000
#define BATCH 4096
#define LN_EPS 1e-5f

#define SCAN_CHUNK 1024
#define NSCAN ((N_NODES + SCAN_CHUNK - 1) / SCAN_CHUNK)   // 147

#define GEMM_BLOCKS ((N_ITEMS + 63) / 64)                 // 782
#define FILL_BLOCKS ((N_EDGES + 255) / 256)               // 18750
#define INIT_BLOCKS 1024
#define COMBO_BLOCKS (GEMM_BLOCKS + FILL_BLOCKS + INIT_BLOCKS)

#define KTILES (F / 32)                                   // 24

#define GATHER_BLOCKS (3 * BATCH / 4)                     // 3072
#define LOSS_BLOCKS (N_ITEMS * D / 4 / 256)               // 3125 exact
#define OUT_BLOCKS (GATHER_BLOCKS + LOSS_BLOCKS)

// ---- scratch (device globals) ----
__device__ float g_e0[N_NODES * D];
__device__ float g_e1[N_NODES * D];
__device__ float g_e2[N_NODES * D];
__device__ float g_e3[N_NODES * D];
__device__ float g_ic[N_ITEMS * D];
__device__ int   g_deg[N_NODES];
__device__ int   g_off[N_NODES + 1];
__device__ int   g_cursor[N_NODES];
__device__ int   g_blksum[NSCAN];
__device__ int   g_csr_src[N_EDGES];
__device__ float g_csr_w[N_EDGES];
__device__ float g_partials[LOSS_BLOCKS];
__device__ int   g_scan_done;
__device__ int   g_loss_done;

// packed f32x2 FMA (sm_103a FFMA2 — exact fp32)
__device__ __forceinline__ unsigned long long pack2(float lo, float hi) {
    unsigned long long r;
    asm("mov.b64 %0, {%1, %2};" : "=l"(r) : "f"(lo), "f"(hi));
    return r;
}
__device__ __forceinline__ void ffma2(unsigned long long& a,
                                      unsigned long long c,
                                      unsigned long long b) {
    asm("fma.rn.f32x2 %0, %1, %2, %0;" : "+l"(a) : "l"(c), "l"(b));
}
__device__ __forceinline__ float2 unpack2(unsigned long long v) {
    float2 r;
    asm("mov.b64 {%0, %1}, %2;" : "=f"(r.x), "=f"(r.y) : "l"(v));
    return r;
}

// ---------------------------------------------------------------------------
__global__ void zero_deg_kernel() {
    int i = blockIdx.x * blockDim.x + threadIdx.x;
    if (i < N_NODES) g_deg[i] = 0;
    if (i == 0) { g_scan_done = 0; g_loss_done = 0; }
}

__global__ void hist_kernel(const int4* __restrict__ dst4) {
    int i = blockIdx.x * blockDim.x + threadIdx.x;
    if (i < N_EDGES / 4) {
        int4 d = dst4[i];
        atomicAdd(&g_deg[d.x], 1);
        atomicAdd(&g_deg[d.y], 1);
        atomicAdd(&g_deg[d.z], 1);
        atomicAdd(&g_deg[d.w], 1);
    }
}

// ---------------------------------------------------------------------------
// fused scan (all 147 blocks co-resident -> spin barrier safe)
// ---------------------------------------------------------------------------
__global__ __launch_bounds__(1024) void scan_fused_kernel() {
    __shared__ int sh[2][1024];
    int t = threadIdx.x;
    int gid = blockIdx.x * SCAN_CHUNK + t;
    int v = (gid < N_NODES) ? g_deg[gid] : 0;

    sh[0][t] = v;
    __syncthreads();
    int cur = 0;
#pragma unroll
    for (int o = 1; o < 1024; o <<= 1) {
        int y = sh[cur][t];
        if (t >= o) y += sh[cur][t - o];
        sh[1 - cur][t] = y;
        __syncthreads();
        cur = 1 - cur;
    }
    int inc = sh[cur][t];

    if (t == 1023) {
        g_blksum[blockIdx.x] = inc;
        __threadfence();
        atomicAdd(&g_scan_done, 1);
    }
    if (t == 0) {
        while (*(volatile int*)&g_scan_done < NSCAN) { }
    }
    __syncthreads();
    __threadfence();

    int b = (t < blockIdx.x) ? ((volatile int*)g_blksum)[t] : 0;
    __syncthreads();
    sh[0][t] = b;
    __syncthreads();
#pragma unroll
    for (int o = 512; o; o >>= 1) {
        if (t < o) sh[0][t] += sh[0][t + o];
        __syncthreads();
    }
    int base = sh[0][0];

    if (gid < N_NODES) {
        int exc = base + inc - v;
        g_off[gid] = exc;
        g_cursor[gid] = exc;
        if (gid == N_NODES - 1) g_off[N_NODES] = base + inc;
    }
}

// ---------------------------------------------------------------------------
// combo: GEMM (4x4 register tile, Cs+Ws double-buffered, 1 barrier/tile)
//        || scalar fill || init
// ---------------------------------------------------------------------------
__global__ __launch_bounds__(256, 4) void combo_kernel(
    const float* __restrict__ cf, const float* __restrict__ Wp,
    const float* __restrict__ bp, const float* __restrict__ wg,
    const float* __restrict__ bg, const float* __restrict__ item_emb,
    const float* __restrict__ user_emb,
    const int* __restrict__ src, const int* __restrict__ dst,
    const float* __restrict__ w) {

    __shared__ float Cs[2][32][68];   // [buf][k][item]
    __shared__ float Ws[2][32][64];   // [buf][k][d]
    __shared__ float gates[64];

    const int bid = blockIdx.x;
    const int tid = threadIdx.x;

    if (bid >= GEMM_BLOCKS) {
        int b2 = bid - GEMM_BLOCKS;
        if (b2 < FILL_BLOCKS) {
            int e = b2 * 256 + tid;
            if (e < N_EDGES) {
                int pos = atomicAdd(&g_cursor[dst[e]], 1);
                g_csr_src[pos] = src[e];
                g_csr_w[pos] = w[e];
            }
        } else {
            int b3 = b2 - FILL_BLOCKS;
            const int n = N_USERS * D / 4;
            const float4* u4 = (const float4*)user_emb;
            float4* e4 = (float4*)g_e0;
            for (int i = b3 * 256 + tid; i < n; i += INIT_BLOCKS * 256)
                e4[i] = u4[i];
        }
        return;
    }

    // ---- fused item GEMM + gate + mix, 4 items x 4 dims per thread ----
    const int d4    = tid & 15;       // d group: dims d4*4 .. d4*4+3
    const int r4    = tid >> 4;       // item group: items r4*4 .. r4*4+3
    const int item0 = bid * 64;

    // Cs staging map (R13-proven): thread (tid,j) -> item it_l + j*8, k = k_l
    const int it_l = tid >> 5;        // 0..7
    const int k_l  = tid & 31;

    // acc2[it*2+j] = packed (out[it][d4*4+2j], out[it][d4*4+2j+1])
    unsigned long long acc2[8];
#pragma unroll
    for (int i = 0; i < 8; i++) acc2[i] = 0ull;
    float gp = 0.f;

    // prologue: stage tile 0 (Cs + Ws)
#pragma unroll
    for (int j = 0; j < 8; j++) {
        int it = it_l + j * 8;
        int item = item0 + it;
        Cs[0][k_l][it] = (item < N_ITEMS) ? cf[item * F + k_l] : 0.f;
    }
#pragma unroll
    for (int j = 0; j < 8; j++) {
        int l = tid + j * 256;        // 0..2047
        int k = l >> 6, dd = l & 63;
        Ws[0][k][dd] = Wp[k * D + dd];
    }
    __syncthreads();

    for (int kt = 0; kt < KTILES; kt++) {
        int cur = kt & 1;
        // prefetch next tile into other buffer
        if (kt + 1 < KTILES) {
            int kbase = (kt + 1) * 32;
#pragma unroll
            for (int j = 0; j < 8; j++) {
                int it = it_l + j * 8;
                int item = item0 + it;
                Cs[1 - cur][k_l][it] =
                    (item < N_ITEMS) ? cf[item * F + kbase + k_l] : 0.f;
            }
#pragma unroll
            for (int j = 0; j < 8; j++) {
                int l = tid + j * 256;
                int k = l >> 6, dd = l & 63;
                Ws[1 - cur][k][dd] = Wp[(kbase + k) * D + dd];
            }
        }

        // gate partial (threads 0..63)
        if (tid < 64) {
#pragma unroll
            for (int k = 0; k < 32; k++)
                gp += Cs[cur][k][tid] * __ldg(&wg[kt * 32 + k]);
        }

        // main loop: per k = 1 LDS.128 (c) + 1 LDS.128 (w) + 8 FFMA2
#pragma unroll
        for (int k = 0; k < 32; k++) {
            float4 cv = *(const float4*)&Cs[cur][k][r4 * 4];
            ulonglong2 wv = *(const ulonglong2*)&Ws[cur][k][d4 * 4];
            unsigned long long c0 = pack2(cv.x, cv.x);
            unsigned long long c1 = pack2(cv.y, cv.y);
            unsigned long long c2 = pack2(cv.z, cv.z);
            unsigned long long c3 = pack2(cv.w, cv.w);
            ffma2(acc2[0], c0, wv.x); ffma2(acc2[1], c0, wv.y);
            ffma2(acc2[2], c1, wv.x); ffma2(acc2[3], c1, wv.y);
            ffma2(acc2[4], c2, wv.x); ffma2(acc2[5], c2, wv.y);
            ffma2(acc2[6], c3, wv.x); ffma2(acc2[7], c3, wv.y);
        }
        __syncthreads();
    }

    if (tid < 64) gates[tid] = 1.f / (1.f + expf(-(gp + bg[0])));
    __syncthreads();

    // epilogue: float4 stores per item row
    const float4 bp4 = *(const float4*)&bp[d4 * 4];
#pragma unroll
    for (int it = 0; it < 4; it++) {
        int item = item0 + r4 * 4 + it;
        if (item < N_ITEMS) {
            float2 lo = unpack2(acc2[it * 2 + 0]);
            float2 hi = unpack2(acc2[it * 2 + 1]);
            float4 ic4 = make_float4(lo.x + bp4.x, lo.y + bp4.y,
                                     hi.x + bp4.z, hi.y + bp4.w);
            *(float4*)&g_ic[item * D + d4 * 4] = ic4;
            float g = gates[r4 * 4 + it];
            float4 ie = *(const float4*)&item_emb[item * D + d4 * 4];
            float4 e4v = make_float4((1.f - g) * ie.x + g * ic4.x,
                                     (1.f - g) * ie.y + g * ic4.y,
                                     (1.f - g) * ie.z + g * ic4.z,
                                     (1.f - g) * ie.w + g * ic4.w);
            *(float4*)&g_e0[(N_USERS + item) * D + d4 * 4] = e4v;
        }
    }
}

// ---------------------------------------------------------------------------
// fused layer: half-warp per node, float4 per lane
// ---------------------------------------------------------------------------
__global__ __launch_bounds__(256) void layer_kernel(int l) {
    const float4* ein;
    float4* eout;
    if (l == 0)      { ein = (const float4*)g_e0; eout = (float4*)g_e1; }
    else if (l == 1) { ein = (const float4*)g_e1; eout = (float4*)g_e2; }
    else             { ein = (const float4*)g_e2; eout = (float4*)g_e3; }

    int warp = threadIdx.x >> 5;
    int lane = threadIdx.x & 31;
    int half = lane >> 4;
    int l16  = lane & 15;
    int node = blockIdx.x * 16 + warp * 2 + half;
    if (node >= N_NODES) return;
    int beg = g_off[node];
    int end = g_off[node + 1];

    float ax = 0.f, ay = 0.f, az = 0.f, aw = 0.f;
    int i = beg;
    for (; i + 4 <= end; i += 4) {
        int s0 = g_csr_src[i + 0], s1 = g_csr_src[i + 1];
        int s2 = g_csr_src[i + 2], s3 = g_csr_src[i + 3];
        float4 x0 = ein[s0 * 16 + l16];
        float4 x1 = ein[s1 * 16 + l16];
        float4 x2 = ein[s2 * 16 + l16];
        float4 x3 = ein[s3 * 16 + l16];
        float w0 = g_csr_w[i + 0], w1 = g_csr_w[i + 1];
        float w2 = g_csr_w[i + 2], w3 = g_csr_w[i + 3];
        ax += w0 * x0.x; ay += w0 * x0.y; az += w0 * x0.z; aw += w0 * x0.w;
        ax += w1 * x1.x; ay += w1 * x1.y; az += w1 * x1.z; aw += w1 * x1.w;
        ax += w2 * x2.x; ay += w2 * x2.y; az += w2 * x2.z; aw += w2 * x2.w;
        ax += w3 * x3.x; ay += w3 * x3.y; az += w3 * x3.z; aw += w3 * x3.w;
    }
    for (; i < end; i++) {
        int s = g_csr_src[i];
        float wv = g_csr_w[i];
        float4 x = ein[s * 16 + l16];
        ax += wv * x.x; ay += wv * x.y; az += wv * x.z; aw += wv * x.w;
    }

    float s = ax + ay + az + aw;
#pragma unroll
    for (int o = 8; o; o >>= 1) s += __shfl_xor_sync(0xFFFFFFFFu, s, o);
    float m = s * (1.f / 64.f);
    float dx = ax - m, dy = ay - m, dz = az - m, dw = aw - m;
    float v = dx * dx + dy * dy + dz * dz + dw * dw;
#pragma unroll
    for (int o = 8; o; o >>= 1) v += __shfl_xor_sync(0xFFFFFFFFu, v, o);
    float rs = rsqrtf(v * (1.f / 64.f) + LN_EPS);

    float4 r = ein[node * 16 + l16];
    eout[node * 16 + l16] =
        make_float4(dx * rs + r.x, dy * rs + r.y, dz * rs + r.z, dw * rs + r.w);
}

// ---------------------------------------------------------------------------
// fused outputs: gathers + loss partials + last-block final reduce
// ---------------------------------------------------------------------------
__global__ __launch_bounds__(256) void out_combo_kernel(
    const int* __restrict__ u, const int* __restrict__ p,
    const int* __restrict__ n, float* __restrict__ out) {
    const int bid = blockIdx.x;
    const int tid = threadIdx.x;

    if (bid < GATHER_BLOCKS) {
        int row  = bid * 4 + (tid >> 6);
        int d    = tid & 63;
        int which = row >> 12;
        int b     = row & 4095;
        int idx;
        if (which == 0)      idx = u[b];
        else if (which == 1) idx = N_USERS + p[b];
        else                 idx = N_USERS + n[b];
        long long o = (long long)idx * D + d;
        out[(long long)row * D + d] =
            (g_e0[o] + g_e1[o] + g_e2[o] + g_e3[o]) * 0.25f;
        return;
    }

    __shared__ float sh[256];
    __shared__ int s_last;
    int lb = bid - GATHER_BLOCKS;
    int i = lb * 256 + tid;
    const float4* e0 = (const float4*)(g_e0 + (long long)N_USERS * D);
    const float4* e1 = (const float4*)(g_e1 + (long long)N_USERS * D);
    const float4* e2 = (const float4*)(g_e2 + (long long)N_USERS * D);
    const float4* e3 = (const float4*)(g_e3 + (long long)N_USERS * D);
    const float4* ic = (const float4*)g_ic;
    float4 a = e0[i], b = e1[i], c = e2[i], d4v = e3[i], f = ic[i];
    float dx = (a.x + b.x + c.x + d4v.x) * 0.25f - f.x;
    float dy = (a.y + b.y + c.y + d4v.y) * 0.25f - f.y;
    float dz = (a.z + b.z + c.z + d4v.z) * 0.25f - f.z;
    float dw = (a.w + b.w + c.w + d4v.w) * 0.25f - f.w;
    sh[tid] = dx * dx + dy * dy + dz * dz + dw * dw;
    __syncthreads();
#pragma unroll
    for (int o = 128; o; o >>= 1) {
        if (tid < o) sh[tid] += sh[tid + o];
        __syncthreads();
    }
    if (tid == 0) {
        g_partials[lb] = sh[0];
        __threadfence();
        int done = atomicAdd(&g_loss_done, 1);
        s_last = (done == LOSS_BLOCKS - 1) ? 1 : 0;
    }
    __syncthreads();

    if (s_last) {
        __threadfence();
        float s = 0.f;
        for (int j = tid; j < LOSS_BLOCKS; j += 256)
            s += ((volatile float*)g_partials)[j];
        sh[tid] = s;
        __syncthreads();
#pragma unroll
        for (int o = 128; o; o >>= 1) {
            if (tid < o) sh[tid] += sh[tid + o];
            __syncthreads();
        }
        if (tid == 0)
            out[3 * BATCH * D] = sh[0] * (0.1f / (float)(N_ITEMS * D));
    }
}

// ---------------------------------------------------------------------------
extern "C" void kernel_launch(void* const* d_in, const int* in_sizes, int n_in,
                              void* d_out, int out_size) {
    const int*   users     = (const int*)  d_in[0];
    const int*   pos_items = (const int*)  d_in[1];
    const int*   neg_items = (const int*)  d_in[2];
    const int*   edge_src  = (const int*)  d_in[3];
    const int*   edge_dst  = (const int*)  d_in[4];
    const float* edge_w    = (const float*)d_in[5];
    const float* user_emb  = (const float*)d_in[6];
    const float* item_emb  = (const float*)d_in[7];
    const float* cf        = (const float*)d_in[8];
    const float* Wp        = (const float*)d_in[9];
    const float* bp        = (const float*)d_in[10];
    const float* wg        = (const float*)d_in[11];
    const float* bg        = (const float*)d_in[12];
    float* out = (float*)d_out;

    zero_deg_kernel<<<(N_NODES + 255) / 256, 256>>>();
    hist_kernel<<<(N_EDGES / 4 + 255) / 256, 256>>>((const int4*)edge_dst);
    scan_fused_kernel<<<NSCAN, 1024>>>();

    combo_kernel<<<COMBO_BLOCKS, 256>>>(cf, Wp, bp, wg, bg, item_emb,
                                        user_emb, edge_src, edge_dst, edge_w);

    const int ln_blocks = (N_NODES + 15) / 16;
    layer_kernel<<<ln_blocks, 256>>>(0);
    layer_kernel<<<ln_blocks, 256>>>(1);
    layer_kernel<<<ln_blocks, 256>>>(2);

    out_combo_kernel<<<OUT_BLOCKS, 256>>>(users, pos_items, neg_items, out);
}

// round 15
// speedup vs baseline: 1.2480x; 1.0209x over previous
#include <cuda_runtime.h>
#include <cuda_bf16.h>

#define N_USERS 100000
#define N_ITEMS 50000
#define N_NODES (N_USERS + N_ITEMS)
#define D 64
#define F 768
#define N_EDGES 4800000
#define BATCH 4096
#define LN_EPS 1e-5f

#define SCAN_CHUNK 1024
#define NSCAN ((N_NODES + SCAN_CHUNK - 1) / SCAN_CHUNK)   // 147

#define GEMM_BLOCKS ((N_ITEMS + 63) / 64)                 // 782
#define FILL_BLOCKS ((N_EDGES + 255) / 256)               // 18750
#define INIT_BLOCKS 1024
#define COMBO_BLOCKS (GEMM_BLOCKS + FILL_BLOCKS + INIT_BLOCKS)

#define KTILES (F / 32)                                   // 24

#define GATHER_BLOCKS (3 * BATCH / 4)                     // 3072
#define LOSS_BLOCKS (N_ITEMS * D / 4 / 256)               // 3125 exact
#define OUT_BLOCKS (GATHER_BLOCKS + LOSS_BLOCKS)

// ---- scratch (device globals) ----
__device__ float g_e0[N_NODES * D];
__device__ float g_e1[N_NODES * D];
__device__ float g_e2[N_NODES * D];
__device__ float g_e3[N_NODES * D];
__device__ float g_ic[N_ITEMS * D];
__device__ int   g_deg[N_NODES];
__device__ int   g_off[N_NODES + 1];
__device__ int   g_cursor[N_NODES];
__device__ int   g_blksum[NSCAN];
__device__ int   g_csr_src[N_EDGES];
__device__ float g_csr_w[N_EDGES];
__device__ float g_partials[LOSS_BLOCKS];
__device__ int   g_scan_done;
__device__ int   g_loss_done;

// ---- tf32 helpers (3xTF32: x = hi + lo, lo ~ 2^-11 of x) ----
__device__ __forceinline__ void split_tf32(float x, unsigned& hi, unsigned& lo) {
    asm("cvt.rna.tf32.f32 %0, %1;" : "=r"(hi) : "f"(x));
    float l = x - __uint_as_float(hi);
    asm("cvt.rna.tf32.f32 %0, %1;" : "=r"(lo) : "f"(l));
}
__device__ __forceinline__ void mma_tf32(float* c, const unsigned* a,
                                         unsigned b0, unsigned b1) {
    asm volatile(
        "mma.sync.aligned.m16n8k8.row.col.f32.tf32.tf32.f32 "
        "{%0,%1,%2,%3}, {%4,%5,%6,%7}, {%8,%9}, {%0,%1,%2,%3};"
        : "+f"(c[0]), "+f"(c[1]), "+f"(c[2]), "+f"(c[3])
        : "r"(a[0]), "r"(a[1]), "r"(a[2]), "r"(a[3]), "r"(b0), "r"(b1));
}

// ---------------------------------------------------------------------------
__global__ void zero_deg_kernel() {
    int i = blockIdx.x * blockDim.x + threadIdx.x;
    if (i < N_NODES) g_deg[i] = 0;
    if (i == 0) { g_scan_done = 0; g_loss_done = 0; }
}

__global__ void hist_kernel(const int4* __restrict__ dst4) {
    int i = blockIdx.x * blockDim.x + threadIdx.x;
    if (i < N_EDGES / 4) {
        int4 d = dst4[i];
        atomicAdd(&g_deg[d.x], 1);
        atomicAdd(&g_deg[d.y], 1);
        atomicAdd(&g_deg[d.z], 1);
        atomicAdd(&g_deg[d.w], 1);
    }
}

// ---------------------------------------------------------------------------
// fused scan (all 147 blocks co-resident -> spin barrier safe)
// ---------------------------------------------------------------------------
__global__ __launch_bounds__(1024) void scan_fused_kernel() {
    __shared__ int sh[2][1024];
    int t = threadIdx.x;
    int gid = blockIdx.x * SCAN_CHUNK + t;
    int v = (gid < N_NODES) ? g_deg[gid] : 0;

    sh[0][t] = v;
    __syncthreads();
    int cur = 0;
#pragma unroll
    for (int o = 1; o < 1024; o <<= 1) {
        int y = sh[cur][t];
        if (t >= o) y += sh[cur][t - o];
        sh[1 - cur][t] = y;
        __syncthreads();
        cur = 1 - cur;
    }
    int inc = sh[cur][t];

    if (t == 1023) {
        g_blksum[blockIdx.x] = inc;
        __threadfence();
        atomicAdd(&g_scan_done, 1);
    }
    if (t == 0) {
        while (*(volatile int*)&g_scan_done < NSCAN) { }
    }
    __syncthreads();
    __threadfence();

    int b = (t < blockIdx.x) ? ((volatile int*)g_blksum)[t] : 0;
    __syncthreads();
    sh[0][t] = b;
    __syncthreads();
#pragma unroll
    for (int o = 512; o; o >>= 1) {
        if (t < o) sh[0][t] += sh[0][t + o];
        __syncthreads();
    }
    int base = sh[0][0];

    if (gid < N_NODES) {
        int exc = base + inc - v;
        g_off[gid] = exc;
        g_cursor[gid] = exc;
        if (gid == N_NODES - 1) g_off[N_NODES] = base + inc;
    }
}

// ---------------------------------------------------------------------------
// combo: GEMM via mma.sync tf32 (3xTF32 compensated) || scalar fill || init
// Warp w: item rows (w&3)*16..+15, dim cols (w>>2)*32..+31 (4 n-tiles of 8)
// ---------------------------------------------------------------------------
__global__ __launch_bounds__(256, 4) void combo_kernel(
    const float* __restrict__ cf, const float* __restrict__ Wp,
    const float* __restrict__ bp, const float* __restrict__ wg,
    const float* __restrict__ bg, const float* __restrict__ item_emb,
    const float* __restrict__ user_emb,
    const int* __restrict__ src, const int* __restrict__ dst,
    const float* __restrict__ w) {

    __shared__ float Cs[2][32][68];   // [buf][k][item], padded
    __shared__ float Ws[2][32][68];   // [buf][k][d],    padded (kills 4-way conflicts)
    __shared__ float gates[64];

    const int bid = blockIdx.x;
    const int tid = threadIdx.x;

    if (bid >= GEMM_BLOCKS) {
        int b2 = bid - GEMM_BLOCKS;
        if (b2 < FILL_BLOCKS) {
            int e = b2 * 256 + tid;
            if (e < N_EDGES) {
                int pos = atomicAdd(&g_cursor[dst[e]], 1);
                g_csr_src[pos] = src[e];
                g_csr_w[pos] = w[e];
            }
        } else {
            int b3 = b2 - FILL_BLOCKS;
            const int n = N_USERS * D / 4;
            const float4* u4 = (const float4*)user_emb;
            float4* e4 = (float4*)g_e0;
            for (int i = b3 * 256 + tid; i < n; i += INIT_BLOCKS * 256)
                e4[i] = u4[i];
        }
        return;
    }

    const int wid   = tid >> 5;
    const int lane  = tid & 31;
    const int lr    = lane >> 2;      // 0..7
    const int lq    = lane & 3;       // 0..3
    const int m0    = (wid & 3) * 16; // item rows of this warp
    const int n0    = (wid >> 2) * 32;// dim cols of this warp
    const int item0 = bid * 64;

    // staging map (proven): thread (tid,j) -> item it_l + j*8, k = k_l
    const int it_l = tid >> 5;
    const int k_l  = tid & 31;

    float acc[4][4];                  // [ntile][c0..c3]
#pragma unroll
    for (int i = 0; i < 4; i++)
#pragma unroll
        for (int j = 0; j < 4; j++) acc[i][j] = 0.f;
    float gp = 0.f;

    // prologue: stage tile 0 (Cs + Ws)
#pragma unroll
    for (int j = 0; j < 8; j++) {
        int it = it_l + j * 8;
        int item = item0 + it;
        Cs[0][k_l][it] = (item < N_ITEMS) ? cf[item * F + k_l] : 0.f;
    }
#pragma unroll
    for (int j = 0; j < 8; j++) {
        int l = tid + j * 256;
        int k = l >> 6, dd = l & 63;
        Ws[0][k][dd] = Wp[k * D + dd];
    }
    __syncthreads();

    for (int kt = 0; kt < KTILES; kt++) {
        int cur = kt & 1;
        if (kt + 1 < KTILES) {
            int kbase = (kt + 1) * 32;
#pragma unroll
            for (int j = 0; j < 8; j++) {
                int it = it_l + j * 8;
                int item = item0 + it;
                Cs[1 - cur][k_l][it] =
                    (item < N_ITEMS) ? cf[item * F + kbase + k_l] : 0.f;
            }
#pragma unroll
            for (int j = 0; j < 8; j++) {
                int l = tid + j * 256;
                int k = l >> 6, dd = l & 63;
                Ws[1 - cur][k][dd] = Wp[(kbase + k) * D + dd];
            }
        }

        // gate partial (threads 0..63)
        if (tid < 64) {
#pragma unroll
            for (int k = 0; k < 32; k++)
                gp += Cs[cur][k][tid] * __ldg(&wg[kt * 32 + k]);
        }

        // 4 k8-steps per 32-k tile
#pragma unroll
        for (int k8 = 0; k8 < 4; k8++) {
            int kc = k8 * 8;
            // A fragment (16x8): a0(r=lr,c=lq) a1(r+8) a2(c+4) a3(r+8,c+4)
            float a0f = Cs[cur][kc + lq    ][m0 + lr    ];
            float a1f = Cs[cur][kc + lq    ][m0 + lr + 8];
            float a2f = Cs[cur][kc + lq + 4][m0 + lr    ];
            float a3f = Cs[cur][kc + lq + 4][m0 + lr + 8];
            unsigned ahi[4], alo[4];
            split_tf32(a0f, ahi[0], alo[0]);
            split_tf32(a1f, ahi[1], alo[1]);
            split_tf32(a2f, ahi[2], alo[2]);
            split_tf32(a3f, ahi[3], alo[3]);
#pragma unroll
            for (int nt = 0; nt < 4; nt++) {
                // B fragment (8x8): b0 k=lq, b1 k=lq+4, n-col = lr
                float b0f = Ws[cur][kc + lq    ][n0 + nt * 8 + lr];
                float b1f = Ws[cur][kc + lq + 4][n0 + nt * 8 + lr];
                unsigned bh0, bl0, bh1, bl1;
                split_tf32(b0f, bh0, bl0);
                split_tf32(b1f, bh1, bl1);
                mma_tf32(acc[nt], ahi, bh0, bh1);   // hi*hi
                mma_tf32(acc[nt], ahi, bl0, bl1);   // hi*lo
                mma_tf32(acc[nt], alo, bh0, bh1);   // lo*hi
            }
        }
        __syncthreads();
    }

    if (tid < 64) gates[tid] = 1.f / (1.f + expf(-(gp + bg[0])));
    __syncthreads();

    // epilogue: c0 (item m0+lr, dim 2lq) c1 (+1) ; c2,c3 same dims, item+8
    int item_a = item0 + m0 + lr;
    int item_b = item_a + 8;
    float ga = gates[m0 + lr];
    float gb = gates[m0 + lr + 8];
#pragma unroll
    for (int nt = 0; nt < 4; nt++) {
        int dd = n0 + nt * 8 + 2 * lq;
        float b0 = bp[dd], b1 = bp[dd + 1];
        if (item_a < N_ITEMS) {
            float ic0 = acc[nt][0] + b0, ic1 = acc[nt][1] + b1;
            *(float2*)&g_ic[item_a * D + dd] = make_float2(ic0, ic1);
            float2 ie = *(const float2*)&item_emb[item_a * D + dd];
            *(float2*)&g_e0[(N_USERS + item_a) * D + dd] =
                make_float2((1.f - ga) * ie.x + ga * ic0,
                            (1.f - ga) * ie.y + ga * ic1);
        }
        if (item_b < N_ITEMS) {
            float ic0 = acc[nt][2] + b0, ic1 = acc[nt][3] + b1;
            *(float2*)&g_ic[item_b * D + dd] = make_float2(ic0, ic1);
            float2 ie = *(const float2*)&item_emb[item_b * D + dd];
            *(float2*)&g_e0[(N_USERS + item_b) * D + dd] =
                make_float2((1.f - gb) * ie.x + gb * ic0,
                            (1.f - gb) * ie.y + gb * ic1);
        }
    }
}

// ---------------------------------------------------------------------------
// fused layer: half-warp per node, float4 per lane
// ---------------------------------------------------------------------------
__global__ __launch_bounds__(256) void layer_kernel(int l) {
    const float4* ein;
    float4* eout;
    if (l == 0)      { ein = (const float4*)g_e0; eout = (float4*)g_e1; }
    else if (l == 1) { ein = (const float4*)g_e1; eout = (float4*)g_e2; }
    else             { ein = (const float4*)g_e2; eout = (float4*)g_e3; }

    int warp = threadIdx.x >> 5;
    int lane = threadIdx.x & 31;
    int half = lane >> 4;
    int l16  = lane & 15;
    int node = blockIdx.x * 16 + warp * 2 + half;
    if (node >= N_NODES) return;
    int beg = g_off[node];
    int end = g_off[node + 1];

    float ax = 0.f, ay = 0.f, az = 0.f, aw = 0.f;
    int i = beg;
    for (; i + 4 <= end; i += 4) {
        int s0 = g_csr_src[i + 0], s1 = g_csr_src[i + 1];
        int s2 = g_csr_src[i + 2], s3 = g_csr_src[i + 3];
        float4 x0 = ein[s0 * 16 + l16];
        float4 x1 = ein[s1 * 16 + l16];
        float4 x2 = ein[s2 * 16 + l16];
        float4 x3 = ein[s3 * 16 + l16];
        float w0 = g_csr_w[i + 0], w1 = g_csr_w[i + 1];
        float w2 = g_csr_w[i + 2], w3 = g_csr_w[i + 3];
        ax += w0 * x0.x; ay += w0 * x0.y; az += w0 * x0.z; aw += w0 * x0.w;
        ax += w1 * x1.x; ay += w1 * x1.y; az += w1 * x1.z; aw += w1 * x1.w;
        ax += w2 * x2.x; ay += w2 * x2.y; az += w2 * x2.z; aw += w2 * x2.w;
        ax += w3 * x3.x; ay += w3 * x3.y; az += w3 * x3.z; aw += w3 * x3.w;
    }
    for (; i < end; i++) {
        int s = g_csr_src[i];
        float wv = g_csr_w[i];
        float4 x = ein[s * 16 + l16];
        ax += wv * x.x; ay += wv * x.y; az += wv * x.z; aw += wv * x.w;
    }

    float s = ax + ay + az + aw;
#pragma unroll
    for (int o = 8; o; o >>= 1) s += __shfl_xor_sync(0xFFFFFFFFu, s, o);
    float m = s * (1.f / 64.f);
    float dx = ax - m, dy = ay - m, dz = az - m, dw = aw - m;
    float v = dx * dx + dy * dy + dz * dz + dw * dw;
#pragma unroll
    for (int o = 8; o; o >>= 1) v += __shfl_xor_sync(0xFFFFFFFFu, v, o);
    float rs = rsqrtf(v * (1.f / 64.f) + LN_EPS);

    float4 r = ein[node * 16 + l16];
    eout[node * 16 + l16] =
        make_float4(dx * rs + r.x, dy * rs + r.y, dz * rs + r.z, dw * rs + r.w);
}

// ---------------------------------------------------------------------------
// fused outputs: gathers + loss partials + last-block final reduce
// ---------------------------------------------------------------------------
__global__ __launch_bounds__(256) void out_combo_kernel(
    const int* __restrict__ u, const int* __restrict__ p,
    const int* __restrict__ n, float* __restrict__ out) {
    const int bid = blockIdx.x;
    const int tid = threadIdx.x;

    if (bid < GATHER_BLOCKS) {
        int row  = bid * 4 + (tid >> 6);
        int d    = tid & 63;
        int which = row >> 12;
        int b     = row & 4095;
        int idx;
        if (which == 0)      idx = u[b];
        else if (which == 1) idx = N_USERS + p[b];
        else                 idx = N_USERS + n[b];
        long long o = (long long)idx * D + d;
        out[(long long)row * D + d] =
            (g_e0[o] + g_e1[o] + g_e2[o] + g_e3[o]) * 0.25f;
        return;
    }

    __shared__ float sh[256];
    __shared__ int s_last;
    int lb = bid - GATHER_BLOCKS;
    int i = lb * 256 + tid;
    const float4* e0 = (const float4*)(g_e0 + (long long)N_USERS * D);
    const float4* e1 = (const float4*)(g_e1 + (long long)N_USERS * D);
    const float4* e2 = (const float4*)(g_e2 + (long long)N_USERS * D);
    const float4* e3 = (const float4*)(g_e3 + (long long)N_USERS * D);
    const float4* ic = (const float4*)g_ic;
    float4 a = e0[i], b = e1[i], c = e2[i], d4v = e3[i], f = ic[i];
    float dx = (a.x + b.x + c.x + d4v.x) * 0.25f - f.x;
    float dy = (a.y + b.y + c.y + d4v.y) * 0.25f - f.y;
    float dz = (a.z + b.z + c.z + d4v.z) * 0.25f - f.z;
    float dw = (a.w + b.w + c.w + d4v.w) * 0.25f - f.w;
    sh[tid] = dx * dx + dy * dy + dz * dz + dw * dw;
    __syncthreads();
#pragma unroll
    for (int o = 128; o; o >>= 1) {
        if (tid < o) sh[tid] += sh[tid + o];
        __syncthreads();
    }
    if (tid == 0) {
        g_partials[lb] = sh[0];
        __threadfence();
        int done = atomicAdd(&g_loss_done, 1);
        s_last = (done == LOSS_BLOCKS - 1) ? 1 : 0;
    }
    __syncthreads();

    if (s_last) {
        __threadfence();
        float s = 0.f;
        for (int j = tid; j < LOSS_BLOCKS; j += 256)
            s += ((volatile float*)g_partials)[j];
        sh[tid] = s;
        __syncthreads();
#pragma unroll
        for (int o = 128; o; o >>= 1) {
            if (tid < o) sh[tid] += sh[tid + o];
            __syncthreads();
        }
        if (tid == 0)
            out[3 * BATCH * D] = sh[0] * (0.1f / (float)(N_ITEMS * D));
    }
}

// ---------------------------------------------------------------------------
extern "C" void kernel_launch(void* const* d_in, const int* in_sizes, int n_in,
                              void* d_out, int out_size) {
    const int*   users     = (const int*)  d_in[0];
    const int*   pos_items = (const int*)  d_in[1];
    const int*   neg_items = (const int*)  d_in[2];
    const int*   edge_src  = (const int*)  d_in[3];
    const int*   edge_dst  = (const int*)  d_in[4];
    const float* edge_w    = (const float*)d_in[5];
    const float* user_emb  = (const float*)d_in[6];
    const float* item_emb  = (const float*)d_in[7];
    const float* cf        = (const float*)d_in[8];
    const float* Wp        = (const float*)d_in[9];
    const float* bp        = (const float*)d_in[10];
    const float* wg        = (const float*)d_in[11];
    const float* bg        = (const float*)d_in[12];
    float* out = (float*)d_out;

    zero_deg_kernel<<<(N_NODES + 255) / 256, 256>>>();
    hist_kernel<<<(N_EDGES / 4 + 255) / 256, 256>>>((const int4*)edge_dst);
    scan_fused_kernel<<<NSCAN, 1024>>>();

    combo_kernel<<<COMBO_BLOCKS, 256>>>(cf, Wp, bp, wg, bg, item_emb,
                                        user_emb, edge_src, edge_dst, edge_w);

    const int ln_blocks = (N_NODES + 15) / 16;
    layer_kernel<<<ln_blocks, 256>>>(0);
    layer_kernel<<<ln_blocks, 256>>>(1);
    layer_kernel<<<ln_blocks, 256>>>(2);

    out_combo_kernel<<<OUT_BLOCKS, 256>>>(users, pos_items, neg_items, out);
}

// round 16
// speedup vs baseline: 1.2832x; 1.0281x over previous
#include <cuda_runtime.h>
#include <cuda_bf16.h>

#define N_USERS 100000
#define N_ITEMS 50000
#define N_NODES (N_USERS + N_ITEMS)
#define D 64
#define F 768
#define N_EDGES 4800000
#define BATCH 4096
#define LN_EPS 1e-5f

#define SCAN_CHUNK 1024
#define NSCAN ((N_NODES + SCAN_CHUNK - 1) / SCAN_CHUNK)   // 147

#define GEMM_BLOCKS ((N_ITEMS + 63) / 64)                 // 782
#define FILL_BLOCKS ((N_EDGES + 255) / 256)               // 18750
#define INIT_BLOCKS 1024
#define COMBO_BLOCKS (GEMM_BLOCKS + FILL_BLOCKS + INIT_BLOCKS)

#define KTILES (F / 32)                                   // 24

#define GATHER_BLOCKS (3 * BATCH / 4)                     // 3072
#define LOSS_BLOCKS (N_ITEMS * D / 4 / 256)               // 3125 exact
#define OUT_BLOCKS (GATHER_BLOCKS + LOSS_BLOCKS)

// ---- scratch (device globals) ----
__device__ float g_e0[N_NODES * D];
__device__ float g_e1[N_NODES * D];
__device__ float g_e2[N_NODES * D];
__device__ float g_e3[N_NODES * D];
__device__ float g_ic[N_ITEMS * D];
__device__ int   g_deg[N_NODES];
__device__ int   g_off[N_NODES + 1];
__device__ int   g_cursor[N_NODES];
__device__ int   g_blksum[NSCAN];
__device__ int   g_csr_src[N_EDGES];
__device__ float g_csr_w[N_EDGES];
__device__ float g_partials[LOSS_BLOCKS];
__device__ int   g_scan_done;
__device__ int   g_loss_done;

// ---- tf32 split via truncation (CUTLASS FastF32 style — no cvt):
// MMA reads fp32 bits as tf32 ignoring low 13 mantissa bits, so
// hi = bits & ~0x1FFF is exactly what the HW would use; lo = x - hi is
// exact in fp32 and can be fed raw (its HW truncation is ~2^-20 rel).
__device__ __forceinline__ void split_tf32(float x, unsigned& hi, unsigned& lo) {
    unsigned xb = __float_as_uint(x);
    hi = xb & 0xFFFFE000u;
    lo = __float_as_uint(x - __uint_as_float(hi));
}
__device__ __forceinline__ void mma_tf32(float* c, const unsigned* a,
                                         unsigned b0, unsigned b1) {
    asm volatile(
        "mma.sync.aligned.m16n8k8.row.col.f32.tf32.tf32.f32 "
        "{%0,%1,%2,%3}, {%4,%5,%6,%7}, {%8,%9}, {%0,%1,%2,%3};"
        : "+f"(c[0]), "+f"(c[1]), "+f"(c[2]), "+f"(c[3])
        : "r"(a[0]), "r"(a[1]), "r"(a[2]), "r"(a[3]), "r"(b0), "r"(b1));
}

// ---------------------------------------------------------------------------
__global__ void zero_deg_kernel() {
    int i = blockIdx.x * blockDim.x + threadIdx.x;
    if (i < N_NODES) g_deg[i] = 0;
    if (i == 0) { g_scan_done = 0; g_loss_done = 0; }
}

__global__ void hist_kernel(const int4* __restrict__ dst4) {
    int i = blockIdx.x * blockDim.x + threadIdx.x;
    if (i < N_EDGES / 4) {
        int4 d = dst4[i];
        atomicAdd(&g_deg[d.x], 1);
        atomicAdd(&g_deg[d.y], 1);
        atomicAdd(&g_deg[d.z], 1);
        atomicAdd(&g_deg[d.w], 1);
    }
}

// ---------------------------------------------------------------------------
// fused scan (all 147 blocks co-resident -> spin barrier safe)
// ---------------------------------------------------------------------------
__global__ __launch_bounds__(1024) void scan_fused_kernel() {
    __shared__ int sh[2][1024];
    int t = threadIdx.x;
    int gid = blockIdx.x * SCAN_CHUNK + t;
    int v = (gid < N_NODES) ? g_deg[gid] : 0;

    sh[0][t] = v;
    __syncthreads();
    int cur = 0;
#pragma unroll
    for (int o = 1; o < 1024; o <<= 1) {
        int y = sh[cur][t];
        if (t >= o) y += sh[cur][t - o];
        sh[1 - cur][t] = y;
        __syncthreads();
        cur = 1 - cur;
    }
    int inc = sh[cur][t];

    if (t == 1023) {
        g_blksum[blockIdx.x] = inc;
        __threadfence();
        atomicAdd(&g_scan_done, 1);
    }
    if (t == 0) {
        while (*(volatile int*)&g_scan_done < NSCAN) { }
    }
    __syncthreads();
    __threadfence();

    int b = (t < blockIdx.x) ? ((volatile int*)g_blksum)[t] : 0;
    __syncthreads();
    sh[0][t] = b;
    __syncthreads();
#pragma unroll
    for (int o = 512; o; o >>= 1) {
        if (t < o) sh[0][t] += sh[0][t + o];
        __syncthreads();
    }
    int base = sh[0][0];

    if (gid < N_NODES) {
        int exc = base + inc - v;
        g_off[gid] = exc;
        g_cursor[gid] = exc;
        if (gid == N_NODES - 1) g_off[N_NODES] = base + inc;
    }
}

// ---------------------------------------------------------------------------
// combo: GEMM via mma.sync tf32 (mask-split 3xTF32) || scalar fill || init
// ---------------------------------------------------------------------------
__global__ __launch_bounds__(256, 4) void combo_kernel(
    const float* __restrict__ cf, const float* __restrict__ Wp,
    const float* __restrict__ bp, const float* __restrict__ wg,
    const float* __restrict__ bg, const float* __restrict__ item_emb,
    const float* __restrict__ user_emb,
    const int* __restrict__ src, const int* __restrict__ dst,
    const float* __restrict__ w) {

    __shared__ float Cs[2][32][68];   // [buf][k][item], padded
    __shared__ float Ws[2][32][68];   // [buf][k][d],    padded
    __shared__ float gates[64];

    const int bid = blockIdx.x;
    const int tid = threadIdx.x;

    if (bid >= GEMM_BLOCKS) {
        int b2 = bid - GEMM_BLOCKS;
        if (b2 < FILL_BLOCKS) {
            int e = b2 * 256 + tid;
            if (e < N_EDGES) {
                int pos = atomicAdd(&g_cursor[dst[e]], 1);
                g_csr_src[pos] = src[e];
                g_csr_w[pos] = w[e];
            }
        } else {
            int b3 = b2 - FILL_BLOCKS;
            const int n = N_USERS * D / 4;
            const float4* u4 = (const float4*)user_emb;
            float4* e4 = (float4*)g_e0;
            for (int i = b3 * 256 + tid; i < n; i += INIT_BLOCKS * 256)
                e4[i] = u4[i];
        }
        return;
    }

    const int wid   = tid >> 5;
    const int lane  = tid & 31;
    const int lr    = lane >> 2;
    const int lq    = lane & 3;
    const int m0    = (wid & 3) * 16;
    const int n0    = (wid >> 2) * 32;
    const int item0 = bid * 64;

    const int it_l = tid >> 5;
    const int k_l  = tid & 31;

    float acc[4][4];
#pragma unroll
    for (int i = 0; i < 4; i++)
#pragma unroll
        for (int j = 0; j < 4; j++) acc[i][j] = 0.f;
    float gp = 0.f;

    // prologue: stage tile 0
#pragma unroll
    for (int j = 0; j < 8; j++) {
        int it = it_l + j * 8;
        int item = item0 + it;
        Cs[0][k_l][it] = (item < N_ITEMS) ? cf[item * F + k_l] : 0.f;
    }
#pragma unroll
    for (int j = 0; j < 8; j++) {
        int l = tid + j * 256;
        int k = l >> 6, dd = l & 63;
        Ws[0][k][dd] = Wp[k * D + dd];
    }
    __syncthreads();

    for (int kt = 0; kt < KTILES; kt++) {
        int cur = kt & 1;
        if (kt + 1 < KTILES) {
            int kbase = (kt + 1) * 32;
#pragma unroll
            for (int j = 0; j < 8; j++) {
                int it = it_l + j * 8;
                int item = item0 + it;
                Cs[1 - cur][k_l][it] =
                    (item < N_ITEMS) ? cf[item * F + kbase + k_l] : 0.f;
            }
#pragma unroll
            for (int j = 0; j < 8; j++) {
                int l = tid + j * 256;
                int k = l >> 6, dd = l & 63;
                Ws[1 - cur][k][dd] = Wp[(kbase + k) * D + dd];
            }
        }

        if (tid < 64) {
#pragma unroll
            for (int k = 0; k < 32; k++)
                gp += Cs[cur][k][tid] * __ldg(&wg[kt * 32 + k]);
        }

#pragma unroll
        for (int k8 = 0; k8 < 4; k8++) {
            int kc = k8 * 8;
            float a0f = Cs[cur][kc + lq    ][m0 + lr    ];
            float a1f = Cs[cur][kc + lq    ][m0 + lr + 8];
            float a2f = Cs[cur][kc + lq + 4][m0 + lr    ];
            float a3f = Cs[cur][kc + lq + 4][m0 + lr + 8];
            unsigned ahi[4], alo[4];
            split_tf32(a0f, ahi[0], alo[0]);
            split_tf32(a1f, ahi[1], alo[1]);
            split_tf32(a2f, ahi[2], alo[2]);
            split_tf32(a3f, ahi[3], alo[3]);
#pragma unroll
            for (int nt = 0; nt < 4; nt++) {
                float b0f = Ws[cur][kc + lq    ][n0 + nt * 8 + lr];
                float b1f = Ws[cur][kc + lq + 4][n0 + nt * 8 + lr];
                unsigned bh0, bl0, bh1, bl1;
                split_tf32(b0f, bh0, bl0);
                split_tf32(b1f, bh1, bl1);
                mma_tf32(acc[nt], ahi, bh0, bh1);
                mma_tf32(acc[nt], ahi, bl0, bl1);
                mma_tf32(acc[nt], alo, bh0, bh1);
            }
        }
        __syncthreads();
    }

    if (tid < 64) gates[tid] = 1.f / (1.f + expf(-(gp + bg[0])));
    __syncthreads();

    int item_a = item0 + m0 + lr;
    int item_b = item_a + 8;
    float ga = gates[m0 + lr];
    float gb = gates[m0 + lr + 8];
#pragma unroll
    for (int nt = 0; nt < 4; nt++) {
        int dd = n0 + nt * 8 + 2 * lq;
        float b0 = bp[dd], b1 = bp[dd + 1];
        if (item_a < N_ITEMS) {
            float ic0 = acc[nt][0] + b0, ic1 = acc[nt][1] + b1;
            *(float2*)&g_ic[item_a * D + dd] = make_float2(ic0, ic1);
            float2 ie = *(const float2*)&item_emb[item_a * D + dd];
            *(float2*)&g_e0[(N_USERS + item_a) * D + dd] =
                make_float2((1.f - ga) * ie.x + ga * ic0,
                            (1.f - ga) * ie.y + ga * ic1);
        }
        if (item_b < N_ITEMS) {
            float ic0 = acc[nt][2] + b0, ic1 = acc[nt][3] + b1;
            *(float2*)&g_ic[item_b * D + dd] = make_float2(ic0, ic1);
            float2 ie = *(const float2*)&item_emb[item_b * D + dd];
            *(float2*)&g_e0[(N_USERS + item_b) * D + dd] =
                make_float2((1.f - gb) * ie.x + gb * ic0,
                            (1.f - gb) * ie.y + gb * ic1);
        }
    }
}

// ---------------------------------------------------------------------------
// fused layer: half-warp per node, float4 per lane
// ---------------------------------------------------------------------------
__global__ __launch_bounds__(256) void layer_kernel(int l) {
    const float4* ein;
    float4* eout;
    if (l == 0)      { ein = (const float4*)g_e0; eout = (float4*)g_e1; }
    else if (l == 1) { ein = (const float4*)g_e1; eout = (float4*)g_e2; }
    else             { ein = (const float4*)g_e2; eout = (float4*)g_e3; }

    int warp = threadIdx.x >> 5;
    int lane = threadIdx.x & 31;
    int half = lane >> 4;
    int l16  = lane & 15;
    int node = blockIdx.x * 16 + warp * 2 + half;
    if (node >= N_NODES) return;
    int beg = g_off[node];
    int end = g_off[node + 1];

    float ax = 0.f, ay = 0.f, az = 0.f, aw = 0.f;
    int i = beg;
    for (; i + 4 <= end; i += 4) {
        int s0 = g_csr_src[i + 0], s1 = g_csr_src[i + 1];
        int s2 = g_csr_src[i + 2], s3 = g_csr_src[i + 3];
        float4 x0 = ein[s0 * 16 + l16];
        float4 x1 = ein[s1 * 16 + l16];
        float4 x2 = ein[s2 * 16 + l16];
        float4 x3 = ein[s3 * 16 + l16];
        float w0 = g_csr_w[i + 0], w1 = g_csr_w[i + 1];
        float w2 = g_csr_w[i + 2], w3 = g_csr_w[i + 3];
        ax += w0 * x0.x; ay += w0 * x0.y; az += w0 * x0.z; aw += w0 * x0.w;
        ax += w1 * x1.x; ay += w1 * x1.y; az += w1 * x1.z; aw += w1 * x1.w;
        ax += w2 * x2.x; ay += w2 * x2.y; az += w2 * x2.z; aw += w2 * x2.w;
        ax += w3 * x3.x; ay += w3 * x3.y; az += w3 * x3.z; aw += w3 * x3.w;
    }
    for (; i < end; i++) {
        int s = g_csr_src[i];
        float wv = g_csr_w[i];
        float4 x = ein[s * 16 + l16];
        ax += wv * x.x; ay += wv * x.y; az += wv * x.z; aw += wv * x.w;
    }

    float s = ax + ay + az + aw;
#pragma unroll
    for (int o = 8; o; o >>= 1) s += __shfl_xor_sync(0xFFFFFFFFu, s, o);
    float m = s * (1.f / 64.f);
    float dx = ax - m, dy = ay - m, dz = az - m, dw = aw - m;
    float v = dx * dx + dy * dy + dz * dz + dw * dw;
#pragma unroll
    for (int o = 8; o; o >>= 1) v += __shfl_xor_sync(0xFFFFFFFFu, v, o);
    float rs = rsqrtf(v * (1.f / 64.f) + LN_EPS);

    float4 r = ein[node * 16 + l16];
    eout[node * 16 + l16] =
        make_float4(dx * rs + r.x, dy * rs + r.y, dz * rs + r.z, dw * rs + r.w);
}

// ---------------------------------------------------------------------------
// fused outputs: gathers + loss partials + last-block final reduce
// ---------------------------------------------------------------------------
__global__ __launch_bounds__(256) void out_combo_kernel(
    const int* __restrict__ u, const int* __restrict__ p,
    const int* __restrict__ n, float* __restrict__ out) {
    const int bid = blockIdx.x;
    const int tid = threadIdx.x;

    if (bid < GATHER_BLOCKS) {
        int row  = bid * 4 + (tid >> 6);
        int d    = tid & 63;
        int which = row >> 12;
        int b     = row & 4095;
        int idx;
        if (which == 0)      idx = u[b];
        else if (which == 1) idx = N_USERS + p[b];
        else                 idx = N_USERS + n[b];
        long long o = (long long)idx * D + d;
        out[(long long)row * D + d] =
            (g_e0[o] + g_e1[o] + g_e2[o] + g_e3[o]) * 0.25f;
        return;
    }

    __shared__ float sh[256];
    __shared__ int s_last;
    int lb = bid - GATHER_BLOCKS;
    int i = lb * 256 + tid;
    const float4* e0 = (const float4*)(g_e0 + (long long)N_USERS * D);
    const float4* e1 = (const float4*)(g_e1 + (long long)N_USERS * D);
    const float4* e2 = (const float4*)(g_e2 + (long long)N_USERS * D);
    const float4* e3 = (const float4*)(g_e3 + (long long)N_USERS * D);
    const float4* ic = (const float4*)g_ic;
    float4 a = e0[i], b = e1[i], c = e2[i], d4v = e3[i], f = ic[i];
    float dx = (a.x + b.x + c.x + d4v.x) * 0.25f - f.x;
    float dy = (a.y + b.y + c.y + d4v.y) * 0.25f - f.y;
    float dz = (a.z + b.z + c.z + d4v.z) * 0.25f - f.z;
    float dw = (a.w + b.w + c.w + d4v.w) * 0.25f - f.w;
    sh[tid] = dx * dx + dy * dy + dz * dz + dw * dw;
    __syncthreads();
#pragma unroll
    for (int o = 128; o; o >>= 1) {
        if (tid < o) sh[tid] += sh[tid + o];
        __syncthreads();
    }
    if (tid == 0) {
        g_partials[lb] = sh[0];
        __threadfence();
        int done = atomicAdd(&g_loss_done, 1);
        s_last = (done == LOSS_BLOCKS - 1) ? 1 : 0;
    }
    __syncthreads();

    if (s_last) {
        __threadfence();
        float s = 0.f;
        for (int j = tid; j < LOSS_BLOCKS; j += 256)
            s += ((volatile float*)g_partials)[j];
        sh[tid] = s;
        __syncthreads();
#pragma unroll
        for (int o = 128; o; o >>= 1) {
            if (tid < o) sh[tid] += sh[tid + o];
            __syncthreads();
        }
        if (tid == 0)
            out[3 * BATCH * D] = sh[0] * (0.1f / (float)(N_ITEMS * D));
    }
}

// ---------------------------------------------------------------------------
extern "C" void kernel_launch(void* const* d_in, const int* in_sizes, int n_in,
                              void* d_out, int out_size) {
    const int*   users     = (const int*)  d_in[0];
    const int*   pos_items = (const int*)  d_in[1];
    const int*   neg_items = (const int*)  d_in[2];
    const int*   edge_src  = (const int*)  d_in[3];
    const int*   edge_dst  = (const int*)  d_in[4];
    const float* edge_w    = (const float*)d_in[5];
    const float* user_emb  = (const float*)d_in[6];
    const float* item_emb  = (const float*)d_in[7];
    const float* cf        = (const float*)d_in[8];
    const float* Wp        = (const float*)d_in[9];
    const float* bp        = (const float*)d_in[10];
    const float* wg        = (const float*)d_in[11];
    const float* bg        = (const float*)d_in[12];
    float* out = (float*)d_out;

    zero_deg_kernel<<<(N_NODES + 255) / 256, 256>>>();
    hist_kernel<<<(N_EDGES / 4 + 255) / 256, 256>>>((const int4*)edge_dst);
    scan_fused_kernel<<<NSCAN, 1024>>>();

    combo_kernel<<<COMBO_BLOCKS, 256>>>(cf, Wp, bp, wg, bg, item_emb,
                                        user_emb, edge_src, edge_dst, edge_w);

    const int ln_blocks = (N_NODES + 15) / 16;
    layer_kernel<<<ln_blocks, 256>>>(0);
    layer_kernel<<<ln_blocks, 256>>>(1);
    layer_kernel<<<ln_blocks, 256>>>(2);

    out_combo_kernel<<<OUT_BLOCKS, 256>>>(users, pos_items, neg_items, out);
}

// round 17
// speedup vs baseline: 1.2904x; 1.0056x over previous
#include <cuda_runtime.h>
#include <cuda_bf16.h>

#define N_USERS 100000
#define N_ITEMS 50000
#define N_NODES (N_USERS + N_ITEMS)
#define D 64
#define F 768
#define N_EDGES 4800000
#define BATCH 4096
#define LN_EPS 1e-5f

#define SCAN_CHUNK 1024
#define NSCAN ((N_NODES + SCAN_CHUNK - 1) / SCAN_CHUNK)   // 147

#define GEMM_BLOCKS ((N_ITEMS + 63) / 64)                 // 782
#define FILL_BLOCKS ((N_EDGES + 255) / 256)               // 18750
#define INIT_BLOCKS 1024
#define COMBO_BLOCKS (GEMM_BLOCKS + FILL_BLOCKS + INIT_BLOCKS)

#define KTILES (F / 32)                                   // 24

#define GATHER_BLOCKS (3 * BATCH / 4)                     // 3072
#define LOSS_BLOCKS (N_ITEMS * D / 4 / 256)               // 3125 exact
#define OUT_BLOCKS (GATHER_BLOCKS + LOSS_BLOCKS)

// ---- scratch (device globals) ----
__device__ float g_e0[N_NODES * D];
__device__ float g_e1[N_NODES * D];
__device__ float g_e2[N_NODES * D];
__device__ float g_e3[N_NODES * D];
__device__ float g_ic[N_ITEMS * D];
__device__ int   g_deg[N_NODES];
__device__ int   g_off[N_NODES + 1];
__device__ int   g_cursor[N_NODES];
__device__ int   g_blksum[NSCAN];
__device__ int   g_csr_src[N_EDGES];
__device__ float g_csr_w[N_EDGES];
__device__ float g_partials[LOSS_BLOCKS];
__device__ int   g_scan_done;
__device__ int   g_loss_done;

// ---- tf32 mask-split (FastF32). 2-pass compensation:
//   D ≈ Ahi·Bhi + Ahi·Blo   (dropped Alo·Bhi term ~2^-12 rel per product
//   → ~1e-4 rel on the F=768 dot; threshold is 1e-3)
__device__ __forceinline__ unsigned tf32_hi(float x) {
    return __float_as_uint(x) & 0xFFFFE000u;
}
__device__ __forceinline__ void split_tf32(float x, unsigned& hi, unsigned& lo) {
    hi = tf32_hi(x);
    lo = __float_as_uint(x - __uint_as_float(hi));
}
__device__ __forceinline__ void mma_tf32(float* c, const unsigned* a,
                                         unsigned b0, unsigned b1) {
    asm volatile(
        "mma.sync.aligned.m16n8k8.row.col.f32.tf32.tf32.f32 "
        "{%0,%1,%2,%3}, {%4,%5,%6,%7}, {%8,%9}, {%0,%1,%2,%3};"
        : "+f"(c[0]), "+f"(c[1]), "+f"(c[2]), "+f"(c[3])
        : "r"(a[0]), "r"(a[1]), "r"(a[2]), "r"(a[3]), "r"(b0), "r"(b1));
}

// ---------------------------------------------------------------------------
__global__ void zero_deg_kernel() {
    int i = blockIdx.x * blockDim.x + threadIdx.x;
    if (i < N_NODES) g_deg[i] = 0;
    if (i == 0) { g_scan_done = 0; g_loss_done = 0; }
}

__global__ void hist_kernel(const int4* __restrict__ dst4) {
    int i = blockIdx.x * blockDim.x + threadIdx.x;
    if (i < N_EDGES / 4) {
        int4 d = dst4[i];
        atomicAdd(&g_deg[d.x], 1);
        atomicAdd(&g_deg[d.y], 1);
        atomicAdd(&g_deg[d.z], 1);
        atomicAdd(&g_deg[d.w], 1);
    }
}

// ---------------------------------------------------------------------------
// fused scan (all 147 blocks co-resident -> spin barrier safe)
// ---------------------------------------------------------------------------
__global__ __launch_bounds__(1024) void scan_fused_kernel() {
    __shared__ int sh[2][1024];
    int t = threadIdx.x;
    int gid = blockIdx.x * SCAN_CHUNK + t;
    int v = (gid < N_NODES) ? g_deg[gid] : 0;

    sh[0][t] = v;
    __syncthreads();
    int cur = 0;
#pragma unroll
    for (int o = 1; o < 1024; o <<= 1) {
        int y = sh[cur][t];
        if (t >= o) y += sh[cur][t - o];
        sh[1 - cur][t] = y;
        __syncthreads();
        cur = 1 - cur;
    }
    int inc = sh[cur][t];

    if (t == 1023) {
        g_blksum[blockIdx.x] = inc;
        __threadfence();
        atomicAdd(&g_scan_done, 1);
    }
    if (t == 0) {
        while (*(volatile int*)&g_scan_done < NSCAN) { }
    }
    __syncthreads();
    __threadfence();

    int b = (t < blockIdx.x) ? ((volatile int*)g_blksum)[t] : 0;
    __syncthreads();
    sh[0][t] = b;
    __syncthreads();
#pragma unroll
    for (int o = 512; o; o >>= 1) {
        if (t < o) sh[0][t] += sh[0][t + o];
        __syncthreads();
    }
    int base = sh[0][0];

    if (gid < N_NODES) {
        int exc = base + inc - v;
        g_off[gid] = exc;
        g_cursor[gid] = exc;
        if (gid == N_NODES - 1) g_off[N_NODES] = base + inc;
    }
}

// ---------------------------------------------------------------------------
// combo: GEMM via mma.sync tf32 (2-pass compensated) || scalar fill || init
// ---------------------------------------------------------------------------
__global__ __launch_bounds__(256, 4) void combo_kernel(
    const float* __restrict__ cf, const float* __restrict__ Wp,
    const float* __restrict__ bp, const float* __restrict__ wg,
    const float* __restrict__ bg, const float* __restrict__ item_emb,
    const float* __restrict__ user_emb,
    const int* __restrict__ src, const int* __restrict__ dst,
    const float* __restrict__ w) {

    __shared__ float Cs[2][32][68];   // [buf][k][item], padded
    __shared__ float Ws[2][32][68];   // [buf][k][d],    padded
    __shared__ float gates[64];

    const int bid = blockIdx.x;
    const int tid = threadIdx.x;

    if (bid >= GEMM_BLOCKS) {
        int b2 = bid - GEMM_BLOCKS;
        if (b2 < FILL_BLOCKS) {
            int e = b2 * 256 + tid;
            if (e < N_EDGES) {
                int pos = atomicAdd(&g_cursor[dst[e]], 1);
                g_csr_src[pos] = src[e];
                g_csr_w[pos] = w[e];
            }
        } else {
            int b3 = b2 - FILL_BLOCKS;
            const int n = N_USERS * D / 4;
            const float4* u4 = (const float4*)user_emb;
            float4* e4 = (float4*)g_e0;
            for (int i = b3 * 256 + tid; i < n; i += INIT_BLOCKS * 256)
                e4[i] = u4[i];
        }
        return;
    }

    const int wid   = tid >> 5;
    const int lane  = tid & 31;
    const int lr    = lane >> 2;
    const int lq    = lane & 3;
    const int m0    = (wid & 3) * 16;
    const int n0    = (wid >> 2) * 32;
    const int item0 = bid * 64;

    const int it_l = tid >> 5;
    const int k_l  = tid & 31;

    float acc[4][4];
#pragma unroll
    for (int i = 0; i < 4; i++)
#pragma unroll
        for (int j = 0; j < 4; j++) acc[i][j] = 0.f;
    float gp = 0.f;

    // prologue: stage tile 0
#pragma unroll
    for (int j = 0; j < 8; j++) {
        int it = it_l + j * 8;
        int item = item0 + it;
        Cs[0][k_l][it] = (item < N_ITEMS) ? cf[item * F + k_l] : 0.f;
    }
#pragma unroll
    for (int j = 0; j < 8; j++) {
        int l = tid + j * 256;
        int k = l >> 6, dd = l & 63;
        Ws[0][k][dd] = Wp[k * D + dd];
    }
    __syncthreads();

    for (int kt = 0; kt < KTILES; kt++) {
        int cur = kt & 1;
        if (kt + 1 < KTILES) {
            int kbase = (kt + 1) * 32;
#pragma unroll
            for (int j = 0; j < 8; j++) {
                int it = it_l + j * 8;
                int item = item0 + it;
                Cs[1 - cur][k_l][it] =
                    (item < N_ITEMS) ? cf[item * F + kbase + k_l] : 0.f;
            }
#pragma unroll
            for (int j = 0; j < 8; j++) {
                int l = tid + j * 256;
                int k = l >> 6, dd = l & 63;
                Ws[1 - cur][k][dd] = Wp[(kbase + k) * D + dd];
            }
        }

        if (tid < 64) {
#pragma unroll
            for (int k = 0; k < 32; k++)
                gp += Cs[cur][k][tid] * __ldg(&wg[kt * 32 + k]);
        }

#pragma unroll
        for (int k8 = 0; k8 < 4; k8++) {
            int kc = k8 * 8;
            // A fragment: hi-parts only (2-pass comp drops Alo·Bhi)
            unsigned ahi[4];
            ahi[0] = tf32_hi(Cs[cur][kc + lq    ][m0 + lr    ]);
            ahi[1] = tf32_hi(Cs[cur][kc + lq    ][m0 + lr + 8]);
            ahi[2] = tf32_hi(Cs[cur][kc + lq + 4][m0 + lr    ]);
            ahi[3] = tf32_hi(Cs[cur][kc + lq + 4][m0 + lr + 8]);
#pragma unroll
            for (int nt = 0; nt < 4; nt++) {
                float b0f = Ws[cur][kc + lq    ][n0 + nt * 8 + lr];
                float b1f = Ws[cur][kc + lq + 4][n0 + nt * 8 + lr];
                unsigned bh0, bl0, bh1, bl1;
                split_tf32(b0f, bh0, bl0);
                split_tf32(b1f, bh1, bl1);
                mma_tf32(acc[nt], ahi, bh0, bh1);   // hi*hi
                mma_tf32(acc[nt], ahi, bl0, bl1);   // hi*lo
            }
        }
        __syncthreads();
    }

    if (tid < 64) gates[tid] = 1.f / (1.f + expf(-(gp + bg[0])));
    __syncthreads();

    int item_a = item0 + m0 + lr;
    int item_b = item_a + 8;
    float ga = gates[m0 + lr];
    float gb = gates[m0 + lr + 8];
#pragma unroll
    for (int nt = 0; nt < 4; nt++) {
        int dd = n0 + nt * 8 + 2 * lq;
        float b0 = bp[dd], b1 = bp[dd + 1];
        if (item_a < N_ITEMS) {
            float ic0 = acc[nt][0] + b0, ic1 = acc[nt][1] + b1;
            *(float2*)&g_ic[item_a * D + dd] = make_float2(ic0, ic1);
            float2 ie = *(const float2*)&item_emb[item_a * D + dd];
            *(float2*)&g_e0[(N_USERS + item_a) * D + dd] =
                make_float2((1.f - ga) * ie.x + ga * ic0,
                            (1.f - ga) * ie.y + ga * ic1);
        }
        if (item_b < N_ITEMS) {
            float ic0 = acc[nt][2] + b0, ic1 = acc[nt][3] + b1;
            *(float2*)&g_ic[item_b * D + dd] = make_float2(ic0, ic1);
            float2 ie = *(const float2*)&item_emb[item_b * D + dd];
            *(float2*)&g_e0[(N_USERS + item_b) * D + dd] =
                make_float2((1.f - gb) * ie.x + gb * ic0,
                            (1.f - gb) * ie.y + gb * ic1);
        }
    }
}

// ---------------------------------------------------------------------------
// fused layer: half-warp per node, float4 per lane
// ---------------------------------------------------------------------------
__global__ __launch_bounds__(256) void layer_kernel(int l) {
    const float4* ein;
    float4* eout;
    if (l == 0)      { ein = (const float4*)g_e0; eout = (float4*)g_e1; }
    else if (l == 1) { ein = (const float4*)g_e1; eout = (float4*)g_e2; }
    else             { ein = (const float4*)g_e2; eout = (float4*)g_e3; }

    int warp = threadIdx.x >> 5;
    int lane = threadIdx.x & 31;
    int half = lane >> 4;
    int l16  = lane & 15;
    int node = blockIdx.x * 16 + warp * 2 + half;
    if (node >= N_NODES) return;
    int beg = g_off[node];
    int end = g_off[node + 1];

    float ax = 0.f, ay = 0.f, az = 0.f, aw = 0.f;
    int i = beg;
    for (; i + 4 <= end; i += 4) {
        int s0 = g_csr_src[i + 0], s1 = g_csr_src[i + 1];
        int s2 = g_csr_src[i + 2], s3 = g_csr_src[i + 3];
        float4 x0 = ein[s0 * 16 + l16];
        float4 x1 = ein[s1 * 16 + l16];
        float4 x2 = ein[s2 * 16 + l16];
        float4 x3 = ein[s3 * 16 + l16];
        float w0 = g_csr_w[i + 0], w1 = g_csr_w[i + 1];
        float w2 = g_csr_w[i + 2], w3 = g_csr_w[i + 3];
        ax += w0 * x0.x; ay += w0 * x0.y; az += w0 * x0.z; aw += w0 * x0.w;
        ax += w1 * x1.x; ay += w1 * x1.y; az += w1 * x1.z; aw += w1 * x1.w;
        ax += w2 * x2.x; ay += w2 * x2.y; az += w2 * x2.z; aw += w2 * x2.w;
        ax += w3 * x3.x; ay += w3 * x3.y; az += w3 * x3.z; aw += w3 * x3.w;
    }
    for (; i < end; i++) {
        int s = g_csr_src[i];
        float wv = g_csr_w[i];
        float4 x = ein[s * 16 + l16];
        ax += wv * x.x; ay += wv * x.y; az += wv * x.z; aw += wv * x.w;
    }

    float s = ax + ay + az + aw;
#pragma unroll
    for (int o = 8; o; o >>= 1) s += __shfl_xor_sync(0xFFFFFFFFu, s, o);
    float m = s * (1.f / 64.f);
    float dx = ax - m, dy = ay - m, dz = az - m, dw = aw - m;
    float v = dx * dx + dy * dy + dz * dz + dw * dw;
#pragma unroll
    for (int o = 8; o; o >>= 1) v += __shfl_xor_sync(0xFFFFFFFFu, v, o);
    float rs = rsqrtf(v * (1.f / 64.f) + LN_EPS);

    float4 r = ein[node * 16 + l16];
    eout[node * 16 + l16] =
        make_float4(dx * rs + r.x, dy * rs + r.y, dz * rs + r.z, dw * rs + r.w);
}

// ---------------------------------------------------------------------------
// fused outputs: gathers + loss partials + last-block final reduce
// ---------------------------------------------------------------------------
__global__ __launch_bounds__(256) void out_combo_kernel(
    const int* __restrict__ u, const int* __restrict__ p,
    const int* __restrict__ n, float* __restrict__ out) {
    const int bid = blockIdx.x;
    const int tid = threadIdx.x;

    if (bid < GATHER_BLOCKS) {
        int row  = bid * 4 + (tid >> 6);
        int d    = tid & 63;
        int which = row >> 12;
        int b     = row & 4095;
        int idx;
        if (which == 0)      idx = u[b];
        else if (which == 1) idx = N_USERS + p[b];
        else                 idx = N_USERS + n[b];
        long long o = (long long)idx * D + d;
        out[(long long)row * D + d] =
            (g_e0[o] + g_e1[o] + g_e2[o] + g_e3[o]) * 0.25f;
        return;
    }

    __shared__ float sh[256];
    __shared__ int s_last;
    int lb = bid - GATHER_BLOCKS;
    int i = lb * 256 + tid;
    const float4* e0 = (const float4*)(g_e0 + (long long)N_USERS * D);
    const float4* e1 = (const float4*)(g_e1 + (long long)N_USERS * D);
    const float4* e2 = (const float4*)(g_e2 + (long long)N_USERS * D);
    const float4* e3 = (const float4*)(g_e3 + (long long)N_USERS * D);
    const float4* ic = (const float4*)g_ic;
    float4 a = e0[i], b = e1[i], c = e2[i], d4v = e3[i], f = ic[i];
    float dx = (a.x + b.x + c.x + d4v.x) * 0.25f - f.x;
    float dy = (a.y + b.y + c.y + d4v.y) * 0.25f - f.y;
    float dz = (a.z + b.z + c.z + d4v.z) * 0.25f - f.z;
    float dw = (a.w + b.w + c.w + d4v.w) * 0.25f - f.w;
    sh[tid] = dx * dx + dy * dy + dz * dz + dw * dw;
    __syncthreads();
#pragma unroll
    for (int o = 128; o; o >>= 1) {
        if (tid < o) sh[tid] += sh[tid + o];
        __syncthreads();
    }
    if (tid == 0) {
        g_partials[lb] = sh[0];
        __threadfence();
        int done = atomicAdd(&g_loss_done, 1);
        s_last = (done == LOSS_BLOCKS - 1) ? 1 : 0;
    }
    __syncthreads();

    if (s_last) {
        __threadfence();
        float s = 0.f;
        for (int j = tid; j < LOSS_BLOCKS; j += 256)
            s += ((volatile float*)g_partials)[j];
        sh[tid] = s;
        __syncthreads();
#pragma unroll
        for (int o = 128; o; o >>= 1) {
            if (tid < o) sh[tid] += sh[tid + o];
            __syncthreads();
        }
        if (tid == 0)
            out[3 * BATCH * D] = sh[0] * (0.1f / (float)(N_ITEMS * D));
    }
}

// ---------------------------------------------------------------------------
extern "C" void kernel_launch(void* const* d_in, const int* in_sizes, int n_in,
                              void* d_out, int out_size) {
    const int*   users     = (const int*)  d_in[0];
    const int*   pos_items = (const int*)  d_in[1];
    const int*   neg_items = (const int*)  d_in[2];
    const int*   edge_src  = (const int*)  d_in[3];
    const int*   edge_dst  = (const int*)  d_in[4];
    const float* edge_w    = (const float*)d_in[5];
    const float* user_emb  = (const float*)d_in[6];
    const float* item_emb  = (const float*)d_in[7];
    const float* cf        = (const float*)d_in[8];
    const float* Wp        = (const float*)d_in[9];
    const float* bp        = (const float*)d_in[10];
    const float* wg        = (const float*)d_in[11];
    const float* bg        = (const float*)d_in[12];
    float* out = (float*)d_out;

    zero_deg_kernel<<<(N_NODES + 255) / 256, 256>>>();
    hist_kernel<<<(N_EDGES / 4 + 255) / 256, 256>>>((const int4*)edge_dst);
    scan_fused_kernel<<<NSCAN, 1024>>>();

    combo_kernel<<<COMBO_BLOCKS, 256>>>(cf, Wp, bp, wg, bg, item_emb,
                                        user_emb, edge_src, edge_dst, edge_w);

    const int ln_blocks = (N_NODES + 15) / 16;
    layer_kernel<<<ln_blocks, 256>>>(0);
    layer_kernel<<<ln_blocks, 256>>>(1);
    layer_kernel<<<ln_blocks, 256>>>(2);

    out_combo_kernel<<<OUT_BLOCKS, 256>>>(users, pos_items, neg_items, out);
}